// round 4
// baseline (speedup 1.0000x reference)
#include <cuda_runtime.h>
#include <math.h>

#define BATCH 256
#define TLEN  192
#define CENC  256
#define NGATE 128   // 4*NECK
#define NECK  32

// ---------------- scratch (static device globals; no allocation) ----------------
__device__ float g_bufy[(size_t)BATCH * CENC * TLEN];          // conv output (B,C,T)
__device__ float g_bufx[(size_t)BATCH * CENC * TLEN];          // interp output (B,C,T)
__device__ float g_pre [(size_t)2 * BATCH * TLEN * NGATE];     // lstm pre-gates
__device__ float g_scale[3][1792];
__device__ int   g_len  [3][1792];
__device__ int   g_src  [3][BATCH][TLEN];
__device__ float g_lam  [3][BATCH][TLEN];
__device__ float g_mean [BATCH];
__device__ float g_istd [BATCH];

// ---------------- threefry2x32 (bit-exact JAX PRNG core) ----------------
__device__ __forceinline__ unsigned tf_rotl(unsigned v, int r) {
    return (v << r) | (v >> (32 - r));
}

__device__ __forceinline__ void threefry2x32(unsigned k0, unsigned k1,
                                             unsigned x0, unsigned x1,
                                             unsigned& o0, unsigned& o1) {
    unsigned ks2 = k0 ^ k1 ^ 0x1BD11BDAu;
    x0 += k0; x1 += k1;
#define TF_RND(r) { x0 += x1; x1 = tf_rotl(x1, r); x1 ^= x0; }
    TF_RND(13) TF_RND(15) TF_RND(26) TF_RND(6)
    x0 += k1;  x1 += ks2 + 1u;
    TF_RND(17) TF_RND(29) TF_RND(16) TF_RND(24)
    x0 += ks2; x1 += k0 + 2u;
    TF_RND(13) TF_RND(15) TF_RND(26) TF_RND(6)
    x0 += k0;  x1 += k1 + 3u;
    TF_RND(17) TF_RND(29) TF_RND(16) TF_RND(24)
    x0 += k1;  x1 += ks2 + 4u;
    TF_RND(13) TF_RND(15) TF_RND(26) TF_RND(6)
#undef TF_RND
    o0 = x0 + ks2;
    o1 = x1 + k0 + 5u;
}

// Partitionable threefry (jax_threefry_partitionable=True, modern-JAX default):
//   random_bits(key,32,shape)[i] = o0 ^ o1 of threefry2x32(key, 0, i)
//   split(key)[i]               = (o0, o1) of threefry2x32(key, 0, i)   (fold-like)
//   fold_in(key, d)             = threefry_2x32(key, [0, d])            (mode-independent)
__device__ __forceinline__ unsigned tf_bits32(unsigned ka, unsigned kb, unsigned i) {
    unsigned o0, o1;
    threefry2x32(ka, kb, 0u, i, o0, o1);
    return o0 ^ o1;
}

// one thread per (layer, segment m): scale draw + length draw
__global__ void rng_bits_kernel() {
    int id = blockIdx.x * blockDim.x + threadIdx.x;
    if (id >= 3 * 1792) return;
    int l = id / 1792, m = id % 1792;

    // key_l = fold_in(key(42), l)
    unsigned ka, kb;
    threefry2x32(0u, 42u, 0u, (unsigned)l, ka, kb);
    // k1, k2 = split(key_l)  (fold-like)
    unsigned k1a, k1b, k2a, k2b;
    threefry2x32(ka, kb, 0u, 0u, k1a, k1b);
    threefry2x32(ka, kb, 0u, 1u, k2a, k2b);

    // uniform(k1, (1792,1), f32, 0.5, 1.5)
    unsigned ub = tf_bits32(k1a, k1b, (unsigned)m);
    float u = __uint_as_float((ub >> 9) | 0x3f800000u) - 1.0f;
    g_scale[l][m] = fmaxf(0.5f, u + 0.5f);

    // randint(k2, (1792,1), 19, 32):
    //   ka2, kb2 = split(k2)          <-- randint's INTERNAL split
    //   higher_bits = random_bits(ka2, 32, shape)
    //   lower_bits  = random_bits(kb2, 32, shape)
    unsigned ha, hb_, la, lb_;
    threefry2x32(k2a, k2b, 0u, 0u, ha, hb_);
    threefry2x32(k2a, k2b, 0u, 1u, la, lb_);
    unsigned hbits = tf_bits32(ha, hb_, (unsigned)m);
    unsigned lbits = tf_bits32(la, lb_, (unsigned)m);
    // span=13, multiplier = (2^16 mod 13)^2 = 9
    unsigned off = ((hbits % 13u) * 9u + (lbits % 13u)) % 13u;
    g_len[l][m] = 19 + (int)off;
}

// one thread per (layer,batch): serial 448-entry scan -> compacted gather map
__global__ void rng_scan_kernel() {
    int id = blockIdx.x * blockDim.x + threadIdx.x;
    if (id >= 3 * BATCH) return;
    int l = id / BATCH, b = id % BATCH;
    int cnt = 0;
    int off = 0;
    for (int s = 0; s < 7; s++) {
        int m = b * 7 + s;
        float scale = g_scale[l][m];
        int   L     = g_len[l][m];
        float Lm1   = (float)(L - 1);
        float offf  = (float)off;
        for (int j = 0; j < 64; j++) {
            float is = (float)j / scale;     // IEEE div, matches XLA
            float fl = floorf(is);
            if (fl < Lm1 && (fl + offf) < 191.0f) {
                if (cnt < TLEN) {
                    g_src[l][b][cnt] = (int)(fl + offf);
                    g_lam[l][b][cnt] = is - fl;
                }
                cnt++;
            }
        }
        off += L;
    }
    for (int t = cnt; t < TLEN; t++) g_src[l][b][t] = -1;
}

// ---------------- conv1d k=5 SAME, (B,Cin,T)->(B,256,T) ----------------
__global__ __launch_bounds__(256)
void conv_kernel(const float* __restrict__ x, const float* __restrict__ w,
                 const float* __restrict__ bias, float* __restrict__ y, int Cin) {
    __shared__ __align__(16) float xs[16][72];       // [ci][t local, 68 used]
    __shared__ __align__(16) float ws[5][16][64];    // [k][ci][co local]
    const int b   = blockIdx.z;
    const int t0  = blockIdx.y * 64;
    const int co0 = blockIdx.x * 64;
    const int tid = threadIdx.x;
    const int ti  = tid & 15;     // time group (4 each)
    const int cj  = tid >> 4;     // cout group (4 each)

    float acc[4][4];
#pragma unroll
    for (int d = 0; d < 4; d++)
#pragma unroll
        for (int e = 0; e < 4; e++) acc[d][e] = 0.f;

    const float* xb = x + (size_t)b * Cin * TLEN;

    for (int c0 = 0; c0 < Cin; c0 += 16) {
        // stage x tile: t in [t0-2, t0+66)
        for (int i = tid; i < 16 * 68; i += 256) {
            int ci = i / 68, tt = i % 68;
            int tg = t0 - 2 + tt;
            float v = 0.f;
            if ((c0 + ci) < Cin && tg >= 0 && tg < TLEN) v = xb[(size_t)(c0 + ci) * TLEN + tg];
            xs[ci][tt] = v;
        }
        // stage weights
        for (int i = tid; i < 5 * 16 * 64; i += 256) {
            int k = i / (16 * 64); int rem = i % (16 * 64);
            int ci = rem / 64, co = rem % 64;
            float v = 0.f;
            if ((c0 + ci) < Cin) v = w[((size_t)k * Cin + (c0 + ci)) * CENC + co0 + co];
            ws[k][ci][co] = v;
        }
        __syncthreads();

#pragma unroll
        for (int ci = 0; ci < 16; ci++) {
            float4 xa = *(const float4*)&xs[ci][ti * 4];
            float4 xc = *(const float4*)&xs[ci][ti * 4 + 4];
            float xw[8] = {xa.x, xa.y, xa.z, xa.w, xc.x, xc.y, xc.z, xc.w};
#pragma unroll
            for (int k = 0; k < 5; k++) {
                float4 wv = *(const float4*)&ws[k][ci][cj * 4];
#pragma unroll
                for (int d = 0; d < 4; d++) {
                    float xv = xw[d + k];
                    acc[d][0] += xv * wv.x;
                    acc[d][1] += xv * wv.y;
                    acc[d][2] += xv * wv.z;
                    acc[d][3] += xv * wv.w;
                }
            }
        }
        __syncthreads();
    }

#pragma unroll
    for (int e = 0; e < 4; e++) {
        int co = co0 + cj * 4 + e;
        float bv = bias[co];
#pragma unroll
        for (int d = 0; d < 4; d++)
            y[((size_t)b * CENC + co) * TLEN + t0 + ti * 4 + d] = acc[d][e] + bv;
    }
}

// ---------------- per-sample mean/istd over (C,T) ----------------
__global__ __launch_bounds__(256)
void stats_kernel(const float* __restrict__ y) {
    int b = blockIdx.x;
    const float* p = y + (size_t)b * CENC * TLEN;
    double s = 0.0, s2 = 0.0;
    for (int i = threadIdx.x; i < CENC * TLEN; i += 256) {
        float v = p[i];
        s += (double)v; s2 += (double)v * (double)v;
    }
    __shared__ double sh[256], sh2[256];
    sh[threadIdx.x] = s; sh2[threadIdx.x] = s2;
    __syncthreads();
    for (int k = 128; k > 0; k >>= 1) {
        if (threadIdx.x < k) { sh[threadIdx.x] += sh[threadIdx.x + k]; sh2[threadIdx.x] += sh2[threadIdx.x + k]; }
        __syncthreads();
    }
    if (threadIdx.x == 0) {
        double m = sh[0] / (double)(CENC * TLEN);
        double var = sh2[0] / (double)(CENC * TLEN) - m * m;
        g_mean[b] = (float)m;
        g_istd[b] = (float)(1.0 / sqrt(var + 1e-5));
    }
}

// ---------------- GN + ReLU + interp gather: (B,C,T)->(B,C,T) ----------------
__global__ __launch_bounds__(256)
void gather_kernel(const float* __restrict__ y, float* __restrict__ xo,
                   const float* __restrict__ gamma, const float* __restrict__ beta,
                   int layer) {
    int b = blockIdx.x, cz = blockIdx.y;
    float mean = g_mean[b], istd = g_istd[b];
    for (int i = threadIdx.x; i < 32 * TLEN; i += 256) {
        int c = cz * 32 + (i / TLEN);
        int t = i % TLEN;
        int s = g_src[layer][b][t];
        float v = 0.f;
        if (s >= 0) {
            float lam = g_lam[layer][b][t];
            const float* yr = y + ((size_t)b * CENC + c) * TLEN;
            float r0 = fmaxf((yr[s]     - mean) * istd * gamma[s]     + beta[s],     0.f);
            float r1 = fmaxf((yr[s + 1] - mean) * istd * gamma[s + 1] + beta[s + 1], 0.f);
            v = (1.f - lam) * r0 + lam * r1;
        }
        xo[((size_t)b * CENC + c) * TLEN + t] = v;
    }
}

// ---------------- LSTM pre-gates GEMM: pre = x^T @ K + bias ----------------
__global__ __launch_bounds__(256)
void gates_kernel(const float* __restrict__ xin,
                  const float* __restrict__ kf, const float* __restrict__ bf,
                  const float* __restrict__ kb, const float* __restrict__ bb,
                  float* __restrict__ pre) {
    __shared__ __align__(16) float as[16][64];
    __shared__ __align__(16) float ks[16][128];
    int dir = blockIdx.y;
    const float* K    = dir ? kb : kf;
    const float* bias = dir ? bb : bf;
    int mt = blockIdx.x;
    int b  = mt / 3;
    int t0 = (mt % 3) * 64;
    int tid = threadIdx.x;
    int mi = tid & 15, ni = tid >> 4;

    float acc[4][8];
#pragma unroll
    for (int d = 0; d < 4; d++)
#pragma unroll
        for (int e = 0; e < 8; e++) acc[d][e] = 0.f;

    const float* xb = xin + (size_t)b * CENC * TLEN;
    for (int c0 = 0; c0 < CENC; c0 += 16) {
        for (int i = tid; i < 16 * 64; i += 256) {
            int cc = i >> 6, mm = i & 63;
            as[cc][mm] = xb[(size_t)(c0 + cc) * TLEN + t0 + mm];
        }
        for (int i = tid; i < 16 * 128; i += 256) {
            int cc = i >> 7, nn = i & 127;
            ks[cc][nn] = K[(size_t)(c0 + cc) * NGATE + nn];
        }
        __syncthreads();
#pragma unroll
        for (int cc = 0; cc < 16; cc++) {
            float4 a4 = *(const float4*)&as[cc][mi * 4];
            float av[4] = {a4.x, a4.y, a4.z, a4.w};
            float4 w0 = *(const float4*)&ks[cc][ni * 8];
            float4 w1 = *(const float4*)&ks[cc][ni * 8 + 4];
            float wv[8] = {w0.x, w0.y, w0.z, w0.w, w1.x, w1.y, w1.z, w1.w};
#pragma unroll
            for (int d = 0; d < 4; d++)
#pragma unroll
                for (int e = 0; e < 8; e++) acc[d][e] += av[d] * wv[e];
        }
        __syncthreads();
    }
#pragma unroll
    for (int d = 0; d < 4; d++) {
        size_t row = ((size_t)dir * BATCH + b) * TLEN + t0 + mi * 4 + d;
#pragma unroll
        for (int e = 0; e < 8; e++)
            pre[row * NGATE + ni * 8 + e] = acc[d][e] + bias[ni * 8 + e];
    }
}

// ---------------- LSTM recurrence: warp per (batch row, dir) ----------------
__device__ __forceinline__ float sigm(float x) { return 1.f / (1.f + expf(-x)); }

__global__ __launch_bounds__(256)
void lstm_kernel(const float* __restrict__ pre,
                 const float* __restrict__ rf, const float* __restrict__ rb,
                 float* __restrict__ out) {
    __shared__ __align__(16) float Rs[32][128];
    int dir = blockIdx.y;
    const float* R = dir ? rb : rf;
    for (int i = threadIdx.x; i < 32 * 128; i += 256) Rs[i >> 7][i & 127] = R[i];
    __syncthreads();

    int warp = threadIdx.x >> 5, lane = threadIdx.x & 31;
    int b = blockIdx.x * 8 + warp;
    float h = 0.f, c = 0.f;
    const float* preb = pre + (((size_t)dir * BATCH + b) * TLEN) * NGATE;

    for (int s = 0; s < TLEN; s++) {
        int t = dir ? (TLEN - 1 - s) : s;
        const float* p = preb + (size_t)t * NGATE;
        float zi = p[lane], zf = p[32 + lane], zg = p[64 + lane], zo = p[96 + lane];
#pragma unroll
        for (int j = 0; j < 32; j++) {
            float hj = __shfl_sync(0xffffffffu, h, j);
            zi += hj * Rs[j][lane];
            zf += hj * Rs[j][32 + lane];
            zg += hj * Rs[j][64 + lane];
            zo += hj * Rs[j][96 + lane];
        }
        c = sigm(zf) * c + sigm(zi) * tanhf(zg);
        h = sigm(zo) * tanhf(c);
        out[((size_t)b * TLEN + t) * 64 + dir * 32 + lane] = h;
    }
}

// ---------------- launch ----------------
extern "C" void kernel_launch(void* const* d_in, const int* in_sizes, int n_in,
                              void* d_out, int out_size) {
    const float* x   = (const float*)d_in[0];
    const float* w0  = (const float*)d_in[1];
    const float* b0  = (const float*)d_in[2];
    const float* w1  = (const float*)d_in[3];
    const float* b1  = (const float*)d_in[4];
    const float* w2  = (const float*)d_in[5];
    const float* b2  = (const float*)d_in[6];
    const float* g0  = (const float*)d_in[7];
    const float* be0 = (const float*)d_in[8];
    const float* g1  = (const float*)d_in[9];
    const float* be1 = (const float*)d_in[10];
    const float* g2  = (const float*)d_in[11];
    const float* be2 = (const float*)d_in[12];
    const float* kf  = (const float*)d_in[13];
    const float* rf  = (const float*)d_in[14];
    const float* bf  = (const float*)d_in[15];
    const float* kb  = (const float*)d_in[16];
    const float* rb  = (const float*)d_in[17];
    const float* bb  = (const float*)d_in[18];

    float *bufy, *bufx, *pre;
    cudaGetSymbolAddress((void**)&bufy, g_bufy);
    cudaGetSymbolAddress((void**)&bufx, g_bufx);
    cudaGetSymbolAddress((void**)&pre,  g_pre);

    rng_bits_kernel<<<21, 256>>>();
    rng_scan_kernel<<<3, 256>>>();

    dim3 gconv(4, 3, BATCH);
    dim3 ggath(BATCH, 8);

    // layer 0 (Cin=257)
    conv_kernel<<<gconv, 256>>>(x, w0, b0, bufy, 257);
    stats_kernel<<<BATCH, 256>>>(bufy);
    gather_kernel<<<ggath, 256>>>(bufy, bufx, g0, be0, 0);
    // layer 1
    conv_kernel<<<gconv, 256>>>(bufx, w1, b1, bufy, 256);
    stats_kernel<<<BATCH, 256>>>(bufy);
    gather_kernel<<<ggath, 256>>>(bufy, bufx, g1, be1, 1);
    // layer 2
    conv_kernel<<<gconv, 256>>>(bufx, w2, b2, bufy, 256);
    stats_kernel<<<BATCH, 256>>>(bufy);
    gather_kernel<<<ggath, 256>>>(bufy, bufx, g2, be2, 2);

    // LSTM
    gates_kernel<<<dim3(768, 2), 256>>>(bufx, kf, bf, kb, bb, pre);
    lstm_kernel<<<dim3(32, 2), 256>>>(pre, rf, rb, (float*)d_out);
}

// round 5
// speedup vs baseline: 1.9827x; 1.9827x over previous
#include <cuda_runtime.h>
#include <cuda_bf16.h>
#include <math.h>

#define BATCH 256
#define TLEN  192
#define CENC  256
#define NGATE 128   // 4*NECK
#define NECK  32
#define TPAD  200   // padded time dim for bf16 activations (t stored at +2)
#define CPAD_MAX 288

// ---------------- scratch (static device globals; no allocation) ----------------
__device__ float g_bufy[(size_t)BATCH * CENC * TLEN];            // conv output (B,C,T)
__device__ float g_bufx[(size_t)BATCH * CENC * TLEN];            // interp output (B,C,T)
__device__ float g_pre [(size_t)2 * BATCH * TLEN * NGATE];       // lstm pre-gates
__device__ __nv_bfloat16 g_ax_hi[(size_t)BATCH * TPAD * CPAD_MAX];
__device__ __nv_bfloat16 g_ax_lo[(size_t)BATCH * TPAD * CPAD_MAX];
__device__ __nv_bfloat16 g_wb_hi[(size_t)5 * CPAD_MAX * 256];
__device__ __nv_bfloat16 g_wb_lo[(size_t)5 * CPAD_MAX * 256];
__device__ float g_gbias[256];
__device__ float g_scale[3][1792];
__device__ int   g_len  [3][1792];
__device__ int   g_src  [3][BATCH][TLEN];
__device__ float g_lam  [3][BATCH][TLEN];
__device__ float g_mean [BATCH];
__device__ float g_istd [BATCH];

// ---------------- threefry2x32 (bit-exact JAX PRNG core) ----------------
__device__ __forceinline__ unsigned tf_rotl(unsigned v, int r) {
    return (v << r) | (v >> (32 - r));
}

__device__ __forceinline__ void threefry2x32(unsigned k0, unsigned k1,
                                             unsigned x0, unsigned x1,
                                             unsigned& o0, unsigned& o1) {
    unsigned ks2 = k0 ^ k1 ^ 0x1BD11BDAu;
    x0 += k0; x1 += k1;
#define TF_RND(r) { x0 += x1; x1 = tf_rotl(x1, r); x1 ^= x0; }
    TF_RND(13) TF_RND(15) TF_RND(26) TF_RND(6)
    x0 += k1;  x1 += ks2 + 1u;
    TF_RND(17) TF_RND(29) TF_RND(16) TF_RND(24)
    x0 += ks2; x1 += k0 + 2u;
    TF_RND(13) TF_RND(15) TF_RND(26) TF_RND(6)
    x0 += k0;  x1 += k1 + 3u;
    TF_RND(17) TF_RND(29) TF_RND(16) TF_RND(24)
    x0 += k1;  x1 += ks2 + 4u;
    TF_RND(13) TF_RND(15) TF_RND(26) TF_RND(6)
#undef TF_RND
    o0 = x0 + ks2;
    o1 = x1 + k0 + 5u;
}

__device__ __forceinline__ unsigned tf_bits32(unsigned ka, unsigned kb, unsigned i) {
    unsigned o0, o1;
    threefry2x32(ka, kb, 0u, i, o0, o1);
    return o0 ^ o1;
}

__global__ void rng_bits_kernel() {
    int id = blockIdx.x * blockDim.x + threadIdx.x;
    if (id >= 3 * 1792) return;
    int l = id / 1792, m = id % 1792;

    unsigned ka, kb;
    threefry2x32(0u, 42u, 0u, (unsigned)l, ka, kb);
    unsigned k1a, k1b, k2a, k2b;
    threefry2x32(ka, kb, 0u, 0u, k1a, k1b);
    threefry2x32(ka, kb, 0u, 1u, k2a, k2b);

    unsigned ub = tf_bits32(k1a, k1b, (unsigned)m);
    float u = __uint_as_float((ub >> 9) | 0x3f800000u) - 1.0f;
    g_scale[l][m] = fmaxf(0.5f, u + 0.5f);

    // randint: internal split of k2, then two bits draws
    unsigned ha, hb_, la, lb_;
    threefry2x32(k2a, k2b, 0u, 0u, ha, hb_);
    threefry2x32(k2a, k2b, 0u, 1u, la, lb_);
    unsigned hbits = tf_bits32(ha, hb_, (unsigned)m);
    unsigned lbits = tf_bits32(la, lb_, (unsigned)m);
    unsigned off = ((hbits % 13u) * 9u + (lbits % 13u)) % 13u;
    g_len[l][m] = 19 + (int)off;
}

__global__ void rng_scan_kernel() {
    int id = blockIdx.x * blockDim.x + threadIdx.x;
    if (id >= 3 * BATCH) return;
    int l = id / BATCH, b = id % BATCH;
    int cnt = 0;
    int off = 0;
    for (int s = 0; s < 7; s++) {
        int m = b * 7 + s;
        float scale = g_scale[l][m];
        int   L     = g_len[l][m];
        float Lm1   = (float)(L - 1);
        float offf  = (float)off;
        for (int j = 0; j < 64; j++) {
            float is = (float)j / scale;
            float fl = floorf(is);
            if (fl < Lm1 && (fl + offf) < 191.0f) {
                if (cnt < TLEN) {
                    g_src[l][b][cnt] = (int)(fl + offf);
                    g_lam[l][b][cnt] = is - fl;
                }
                cnt++;
            }
        }
        off += L;
    }
    for (int t = cnt; t < TLEN; t++) g_src[l][b][t] = -1;
}

// ---------------- prep_x: fp32 (B,Csrc,192) -> bf16 hi/lo (B,200,Cpad), t shifted +2 ----------------
__global__ __launch_bounds__(256)
void prep_x_kernel(const float* __restrict__ src, int Csrc, int Cpad,
                   __nv_bfloat16* __restrict__ dhi, __nv_bfloat16* __restrict__ dlo) {
    __shared__ float s[32][65];
    int c0 = blockIdx.x * 32;
    int t0 = blockIdx.y * 64;
    int b  = blockIdx.z;
    int tid = threadIdx.x;
    // load: 32 c x 64 t (t index = dst t; src time = td-2)
    for (int i = tid; i < 32 * 64; i += 256) {
        int ci = i >> 6, tt = i & 63;
        int tsrc = t0 + tt - 2;
        float v = 0.f;
        int c = c0 + ci;
        if (c < Csrc && tsrc >= 0 && tsrc < TLEN)
            v = src[((size_t)b * Csrc + c) * TLEN + tsrc];
        s[ci][tt] = v;
    }
    __syncthreads();
    // store transposed: rows td, cols c
    for (int i = tid; i < 64 * 32; i += 256) {
        int tdl = i >> 5, cl = i & 31;
        int td = t0 + tdl;
        if (td < TPAD) {
            float f = s[cl][tdl];
            __nv_bfloat16 hi = __float2bfloat16(f);
            float lo = f - __bfloat162float(hi);
            size_t o = ((size_t)b * TPAD + td) * Cpad + c0 + cl;
            dhi[o] = hi;
            dlo[o] = __float2bfloat16(lo);
        }
    }
}

// ---------------- prep_w: fp32 (taps,Csrc,256) -> bf16 hi/lo (taps,Cpad,256) ----------------
__global__ __launch_bounds__(256)
void prep_w_kernel(const float* __restrict__ w, int taps, int Csrc, int Cpad) {
    int n = gridDim.x * blockDim.x;
    int total = taps * Cpad * 256;
    for (int i = blockIdx.x * blockDim.x + threadIdx.x; i < total; i += n) {
        int tap = i / (Cpad * 256);
        int rem = i % (Cpad * 256);
        int c = rem / 256, co = rem % 256;
        float v = (c < Csrc) ? w[((size_t)tap * Csrc + c) * 256 + co] : 0.f;
        __nv_bfloat16 hi = __float2bfloat16(v);
        float lo = v - __bfloat162float(hi);
        g_wb_hi[i] = hi;
        g_wb_lo[i] = __float2bfloat16(lo);
    }
}

// ---------------- prep_gw: build gates weight (1,256,256) + bias ----------------
__global__ __launch_bounds__(256)
void prep_gw_kernel(const float* __restrict__ kf, const float* __restrict__ bf,
                    const float* __restrict__ kb, const float* __restrict__ bb) {
    int i = blockIdx.x * blockDim.x + threadIdx.x;
    if (i < 256 * 256) {
        int c = i / 256, nn = i % 256;
        float v = (nn < 128) ? kf[(size_t)c * 128 + nn] : kb[(size_t)c * 128 + (nn - 128)];
        __nv_bfloat16 hi = __float2bfloat16(v);
        float lo = v - __bfloat162float(hi);
        g_wb_hi[i] = hi;
        g_wb_lo[i] = __float2bfloat16(lo);
        if (i < 256) g_gbias[i] = (i < 128) ? bf[i] : bb[i - 128];
    }
}

// ---------------- tensor-core GEMM: conv (5 taps) or gates (1 tap) ----------------
// A: bf16 (B, 200, Cpad), rows t (time stored +2), cols c
// W: bf16 (taps, Cpad, 256), rows c, cols co
// 3-split accumulation: hi*hi + hi*lo + lo*hi in fp32
// mode 0: out[b][co][t] = acc + bias[co]   (y, (B,256,192))
// mode 1: out[((dir*B+b)*192+t)*128 + g] = acc + gbias[co], dir=co>>7
__global__ __launch_bounds__(256)
void mma_kernel(const __nv_bfloat16* __restrict__ Ahi, const __nv_bfloat16* __restrict__ Alo,
                const __nv_bfloat16* __restrict__ Whi, const __nv_bfloat16* __restrict__ Wlo,
                const float* __restrict__ bias, float* __restrict__ out,
                int Cpad, int tap_count, int tap_offset, int mode) {
    __shared__ __nv_bfloat16 s_a[68][40];          // [t local][k], pad 40
    __shared__ __nv_bfloat16 s_b[5][32][136];      // [tap][k][n], pad 136

    const int bn = blockIdx.x;      // n tile (128 wide)
    const int bm = blockIdx.y;      // m tile (64 wide)
    const int bb = blockIdx.z;      // batch
    const int tid  = threadIdx.x;
    const int wid  = tid >> 5;
    const int lane = tid & 31;
    const int warp_m = wid >> 2;    // 0..1
    const int warp_n = wid & 3;     // 0..3
    const int t0 = bm * 64;
    const int n0 = bn * 128;

    float acc[2][4][4];
#pragma unroll
    for (int i = 0; i < 2; i++)
#pragma unroll
        for (int j = 0; j < 4; j++)
#pragma unroll
            for (int k = 0; k < 4; k++) acc[i][j][k] = 0.f;

    const int kchunks = Cpad >> 5;
    const int b_loads = tap_count * 512;   // uint4 count for B staging

    for (int split = 0; split < 3; split++) {
        const __nv_bfloat16* A = (split < 2) ? Ahi : Alo;
        const __nv_bfloat16* W = (split == 1) ? Wlo : Whi;
        for (int kc = 0; kc < kchunks; kc++) {
            int k0 = kc * 32;
            __syncthreads();
            // stage A: 68 rows (t0..t0+67) x 32 k
            {
                const uint4* src = (const uint4*)(A + ((size_t)bb * TPAD + t0) * Cpad + k0);
                int row_stride_u4 = Cpad >> 3;   // uint4 per row
                for (int i = tid; i < 68 * 4; i += 256) {
                    int r = i >> 2, q = i & 3;
                    uint4 v = src[(size_t)r * row_stride_u4 + q];
                    *(uint4*)&s_a[r][q * 8] = v;
                }
            }
            // stage B: tap_count x 32 k x 128 n
            {
                for (int i = tid; i < b_loads; i += 256) {
                    int tp = i >> 9;
                    int r  = (i >> 4) & 31;
                    int q  = i & 15;
                    const uint4* src = (const uint4*)(W + ((size_t)tp * Cpad + k0 + r) * 256 + n0);
                    *(uint4*)&s_b[tp][r][q * 8] = src[q];
                }
            }
            __syncthreads();

            for (int tp = 0; tp < tap_count; tp++) {
                int cshift = tap_offset + tp;
#pragma unroll
                for (int kstep = 0; kstep < 2; kstep++) {
                    // A frags: 2 m-tiles
                    unsigned a[2][4];
#pragma unroll
                    for (int mt = 0; mt < 2; mt++) {
                        int row = warp_m * 32 + mt * 16 + cshift + (lane & 15);
                        int col = kstep * 16 + ((lane >> 4) * 8);
                        unsigned addr = (unsigned)__cvta_generic_to_shared(&s_a[row][col]);
                        asm volatile("ldmatrix.sync.aligned.m8n8.x4.shared.b16 {%0,%1,%2,%3}, [%4];"
                                     : "=r"(a[mt][0]), "=r"(a[mt][1]), "=r"(a[mt][2]), "=r"(a[mt][3])
                                     : "r"(addr));
                    }
                    // B frags: 4 n-tiles via 2 trans x4
                    unsigned bfr[4][2];
#pragma unroll
                    for (int np = 0; np < 2; np++) {
                        int row = kstep * 16 + (lane & 7) + ((lane & 8) ? 8 : 0);
                        int col = warp_n * 32 + np * 16 + ((lane >= 16) ? 8 : 0);
                        unsigned addr = (unsigned)__cvta_generic_to_shared(&s_b[tp][row][col]);
                        unsigned r0, r1, r2, r3;
                        asm volatile("ldmatrix.sync.aligned.m8n8.x4.trans.shared.b16 {%0,%1,%2,%3}, [%4];"
                                     : "=r"(r0), "=r"(r1), "=r"(r2), "=r"(r3)
                                     : "r"(addr));
                        bfr[np * 2 + 0][0] = r0; bfr[np * 2 + 0][1] = r1;
                        bfr[np * 2 + 1][0] = r2; bfr[np * 2 + 1][1] = r3;
                    }
#pragma unroll
                    for (int mt = 0; mt < 2; mt++)
#pragma unroll
                        for (int nt = 0; nt < 4; nt++) {
                            asm volatile(
                                "mma.sync.aligned.m16n8k16.row.col.f32.bf16.bf16.f32 "
                                "{%0,%1,%2,%3},{%4,%5,%6,%7},{%8,%9},{%0,%1,%2,%3};"
                                : "+f"(acc[mt][nt][0]), "+f"(acc[mt][nt][1]),
                                  "+f"(acc[mt][nt][2]), "+f"(acc[mt][nt][3])
                                : "r"(a[mt][0]), "r"(a[mt][1]), "r"(a[mt][2]), "r"(a[mt][3]),
                                  "r"(bfr[nt][0]), "r"(bfr[nt][1]));
                        }
                }
            }
        }
    }

    // epilogue
    int gid = lane >> 2, tig = lane & 3;
#pragma unroll
    for (int mt = 0; mt < 2; mt++) {
#pragma unroll
        for (int nt = 0; nt < 4; nt++) {
            int t  = t0 + warp_m * 32 + mt * 16 + gid;
            int co = n0 + warp_n * 32 + nt * 8 + tig * 2;
            float bv0 = bias[co], bv1 = bias[co + 1];
            if (mode == 0) {
                float* yp0 = out + ((size_t)bb * 256 + co) * TLEN;
                float* yp1 = yp0 + TLEN;
                yp0[t]     = acc[mt][nt][0] + bv0;
                yp1[t]     = acc[mt][nt][1] + bv1;
                yp0[t + 8] = acc[mt][nt][2] + bv0;
                yp1[t + 8] = acc[mt][nt][3] + bv1;
            } else {
                int dir0 = co >> 7, g0 = co & 127;
                int dir1 = (co + 1) >> 7, g1 = (co + 1) & 127;
                size_t r0 = ((size_t)(dir0 * BATCH + bb) * TLEN + t) * NGATE + g0;
                size_t r1 = ((size_t)(dir1 * BATCH + bb) * TLEN + t) * NGATE + g1;
                out[r0] = acc[mt][nt][0] + bv0;
                out[r1] = acc[mt][nt][1] + bv1;
                size_t r2 = ((size_t)(dir0 * BATCH + bb) * TLEN + t + 8) * NGATE + g0;
                size_t r3 = ((size_t)(dir1 * BATCH + bb) * TLEN + t + 8) * NGATE + g1;
                out[r2] = acc[mt][nt][2] + bv0;
                out[r3] = acc[mt][nt][3] + bv1;
            }
        }
    }
}

// ---------------- per-sample mean/istd over (C,T), fp32 ----------------
__global__ __launch_bounds__(256)
void stats_kernel(const float* __restrict__ y) {
    int b = blockIdx.x;
    const float4* p = (const float4*)(y + (size_t)b * CENC * TLEN);
    float s0 = 0.f, s1 = 0.f, q0 = 0.f, q1 = 0.f;
    for (int i = threadIdx.x; i < CENC * TLEN / 4; i += 512) {
        float4 v = p[i];
        s0 += v.x + v.y;
        s1 += v.z + v.w;
        q0 = fmaf(v.x, v.x, fmaf(v.y, v.y, q0));
        q1 = fmaf(v.z, v.z, fmaf(v.w, v.w, q1));
    }
    for (int i = threadIdx.x + 256; i < CENC * TLEN / 4; i += 512) {
        float4 v = p[i];
        s0 += v.x + v.y;
        s1 += v.z + v.w;
        q0 = fmaf(v.x, v.x, fmaf(v.y, v.y, q0));
        q1 = fmaf(v.z, v.z, fmaf(v.w, v.w, q1));
    }
    float s = s0 + s1, q = q0 + q1;
    __shared__ float sh[256], sh2[256];
    sh[threadIdx.x] = s; sh2[threadIdx.x] = q;
    __syncthreads();
    for (int k = 128; k > 0; k >>= 1) {
        if (threadIdx.x < k) { sh[threadIdx.x] += sh[threadIdx.x + k]; sh2[threadIdx.x] += sh2[threadIdx.x + k]; }
        __syncthreads();
    }
    if (threadIdx.x == 0) {
        float m = sh[0] / (float)(CENC * TLEN);
        float var = sh2[0] / (float)(CENC * TLEN) - m * m;
        g_mean[b] = m;
        g_istd[b] = rsqrtf(var + 1e-5f);
    }
}

// ---------------- GN + ReLU + interp gather: (B,C,T)->(B,C,T) ----------------
__global__ __launch_bounds__(256)
void gather_kernel(const float* __restrict__ y, float* __restrict__ xo,
                   const float* __restrict__ gamma, const float* __restrict__ beta,
                   int layer) {
    int b = blockIdx.x, cz = blockIdx.y;
    float mean = g_mean[b], istd = g_istd[b];
    for (int i = threadIdx.x; i < 32 * TLEN; i += 256) {
        int c = cz * 32 + (i / TLEN);
        int t = i % TLEN;
        int s = g_src[layer][b][t];
        float v = 0.f;
        if (s >= 0) {
            float lam = g_lam[layer][b][t];
            const float* yr = y + ((size_t)b * CENC + c) * TLEN;
            float r0 = fmaxf((yr[s]     - mean) * istd * gamma[s]     + beta[s],     0.f);
            float r1 = fmaxf((yr[s + 1] - mean) * istd * gamma[s + 1] + beta[s + 1], 0.f);
            v = (1.f - lam) * r0 + lam * r1;
        }
        xo[((size_t)b * CENC + c) * TLEN + t] = v;
    }
}

// ---------------- LSTM recurrence: warp per (batch row, dir) ----------------
__device__ __forceinline__ float sigm(float x) { return 1.f / (1.f + expf(-x)); }

__global__ __launch_bounds__(256)
void lstm_kernel(const float* __restrict__ pre,
                 const float* __restrict__ rf, const float* __restrict__ rb,
                 float* __restrict__ out) {
    __shared__ __align__(16) float Rs[32][128];
    int dir = blockIdx.y;
    const float* R = dir ? rb : rf;
    for (int i = threadIdx.x; i < 32 * 128; i += 256) Rs[i >> 7][i & 127] = R[i];
    __syncthreads();

    int warp = threadIdx.x >> 5, lane = threadIdx.x & 31;
    int b = blockIdx.x * 8 + warp;
    float h = 0.f, c = 0.f;
    const float* preb = pre + (((size_t)dir * BATCH + b) * TLEN) * NGATE;

    for (int s = 0; s < TLEN; s++) {
        int t = dir ? (TLEN - 1 - s) : s;
        const float* p = preb + (size_t)t * NGATE;
        float zi = p[lane], zf = p[32 + lane], zg = p[64 + lane], zo = p[96 + lane];
#pragma unroll
        for (int j = 0; j < 32; j++) {
            float hj = __shfl_sync(0xffffffffu, h, j);
            zi += hj * Rs[j][lane];
            zf += hj * Rs[j][32 + lane];
            zg += hj * Rs[j][64 + lane];
            zo += hj * Rs[j][96 + lane];
        }
        c = sigm(zf) * c + sigm(zi) * tanhf(zg);
        h = sigm(zo) * tanhf(c);
        out[((size_t)b * TLEN + t) * 64 + dir * 32 + lane] = h;
    }
}

// ---------------- launch ----------------
extern "C" void kernel_launch(void* const* d_in, const int* in_sizes, int n_in,
                              void* d_out, int out_size) {
    const float* x   = (const float*)d_in[0];
    const float* w0  = (const float*)d_in[1];
    const float* b0  = (const float*)d_in[2];
    const float* w1  = (const float*)d_in[3];
    const float* b1  = (const float*)d_in[4];
    const float* w2  = (const float*)d_in[5];
    const float* b2  = (const float*)d_in[6];
    const float* g0  = (const float*)d_in[7];
    const float* be0 = (const float*)d_in[8];
    const float* g1  = (const float*)d_in[9];
    const float* be1 = (const float*)d_in[10];
    const float* g2  = (const float*)d_in[11];
    const float* be2 = (const float*)d_in[12];
    const float* kf  = (const float*)d_in[13];
    const float* rf  = (const float*)d_in[14];
    const float* bf  = (const float*)d_in[15];
    const float* kb  = (const float*)d_in[16];
    const float* rb  = (const float*)d_in[17];
    const float* bb  = (const float*)d_in[18];

    float *bufy, *bufx, *pre, *gbias;
    __nv_bfloat16 *axh, *axl, *wbh, *wbl;
    cudaGetSymbolAddress((void**)&bufy, g_bufy);
    cudaGetSymbolAddress((void**)&bufx, g_bufx);
    cudaGetSymbolAddress((void**)&pre,  g_pre);
    cudaGetSymbolAddress((void**)&gbias, g_gbias);
    cudaGetSymbolAddress((void**)&axh, g_ax_hi);
    cudaGetSymbolAddress((void**)&axl, g_ax_lo);
    cudaGetSymbolAddress((void**)&wbh, g_wb_hi);
    cudaGetSymbolAddress((void**)&wbl, g_wb_lo);

    rng_bits_kernel<<<21, 256>>>();
    rng_scan_kernel<<<3, 256>>>();

    dim3 gmma(2, 3, BATCH);
    dim3 ggath(BATCH, 8);

    // layer 0 (Csrc=257, Cpad=288)
    prep_w_kernel<<<288, 256>>>(w0, 5, 257, 288);
    prep_x_kernel<<<dim3(9, 4, BATCH), 256>>>(x, 257, 288, axh, axl);
    mma_kernel<<<gmma, 256>>>(axh, axl, wbh, wbl, b0, bufy, 288, 5, 0, 0);
    stats_kernel<<<BATCH, 256>>>(bufy);
    gather_kernel<<<ggath, 256>>>(bufy, bufx, g0, be0, 0);
    // layer 1
    prep_w_kernel<<<256, 256>>>(w1, 5, 256, 256);
    prep_x_kernel<<<dim3(8, 4, BATCH), 256>>>(bufx, 256, 256, axh, axl);
    mma_kernel<<<gmma, 256>>>(axh, axl, wbh, wbl, b1, bufy, 256, 5, 0, 0);
    stats_kernel<<<BATCH, 256>>>(bufy);
    gather_kernel<<<ggath, 256>>>(bufy, bufx, g1, be1, 1);
    // layer 2
    prep_w_kernel<<<256, 256>>>(w2, 5, 256, 256);
    prep_x_kernel<<<dim3(8, 4, BATCH), 256>>>(bufx, 256, 256, axh, axl);
    mma_kernel<<<gmma, 256>>>(axh, axl, wbh, wbl, b2, bufy, 256, 5, 0, 0);
    stats_kernel<<<BATCH, 256>>>(bufy);
    gather_kernel<<<ggath, 256>>>(bufy, bufx, g2, be2, 2);

    // LSTM pre-gates via the same MMA kernel (1 tap, offset 2, mode 1)
    prep_x_kernel<<<dim3(8, 4, BATCH), 256>>>(bufx, 256, 256, axh, axl);
    prep_gw_kernel<<<256, 256>>>(kf, bf, kb, bb);
    mma_kernel<<<gmma, 256>>>(axh, axl, wbh, wbl, gbias, pre, 256, 1, 2, 1);

    lstm_kernel<<<dim3(32, 2), 256>>>(pre, rf, rb, (float*)d_out);
}

// round 7
// speedup vs baseline: 2.1986x; 1.1089x over previous
#include <cuda_runtime.h>
#include <cuda_bf16.h>
#include <math.h>
#include <stdint.h>

#define BATCH 256
#define TLEN  192
#define CENC  256
#define NGATE 128
#define NECK  32
#define TPAD  200
#define CPAD_MAX 320

// ---------------- scratch ----------------
__device__ float g_bufy[(size_t)BATCH * CENC * TLEN];            // conv output (B,C,T)
__device__ float g_pre [(size_t)2 * BATCH * TLEN * NGATE];       // lstm pre-gates
__device__ __nv_bfloat16 g_ax_hi[(size_t)BATCH * TPAD * CPAD_MAX];
__device__ __nv_bfloat16 g_ax_lo[(size_t)BATCH * TPAD * CPAD_MAX];
__device__ __nv_bfloat16 g_wb_hi[(size_t)5 * CPAD_MAX * 256];    // (tap, c, co)
__device__ __nv_bfloat16 g_wb_lo[(size_t)5 * CPAD_MAX * 256];
__device__ float g_gbias[256];
__device__ float g_scale[3][1792];
__device__ int   g_len  [3][1792];
__device__ int   g_src  [3][BATCH][TLEN];
__device__ float g_lam  [3][BATCH][TLEN];
__device__ float g_mean [BATCH];
__device__ float g_istd [BATCH];

// ---------------- cp.async helpers ----------------
#define CP16(dst, src) \
    asm volatile("cp.async.cg.shared.global [%0], [%1], 16;" :: "r"(dst), "l"(src))
#define CPCOMMIT() asm volatile("cp.async.commit_group;")
#define CPWAIT1()  asm volatile("cp.async.wait_group 1;")
#define CPWAIT0()  asm volatile("cp.async.wait_group 0;")

__device__ __forceinline__ uint32_t smem_u32(const void* p) {
    uint32_t a;
    asm("{ .reg .u64 t; cvta.to.shared.u64 t, %1; cvt.u32.u64 %0, t; }" : "=r"(a) : "l"(p));
    return a;
}

// ---------------- threefry2x32 (bit-exact JAX PRNG) ----------------
__device__ __forceinline__ unsigned tf_rotl(unsigned v, int r) {
    return (v << r) | (v >> (32 - r));
}
__device__ __forceinline__ void threefry2x32(unsigned k0, unsigned k1,
                                             unsigned x0, unsigned x1,
                                             unsigned& o0, unsigned& o1) {
    unsigned ks2 = k0 ^ k1 ^ 0x1BD11BDAu;
    x0 += k0; x1 += k1;
#define TF_RND(r) { x0 += x1; x1 = tf_rotl(x1, r); x1 ^= x0; }
    TF_RND(13) TF_RND(15) TF_RND(26) TF_RND(6)
    x0 += k1;  x1 += ks2 + 1u;
    TF_RND(17) TF_RND(29) TF_RND(16) TF_RND(24)
    x0 += ks2; x1 += k0 + 2u;
    TF_RND(13) TF_RND(15) TF_RND(26) TF_RND(6)
    x0 += k0;  x1 += k1 + 3u;
    TF_RND(17) TF_RND(29) TF_RND(16) TF_RND(24)
    x0 += k1;  x1 += ks2 + 4u;
    TF_RND(13) TF_RND(15) TF_RND(26) TF_RND(6)
#undef TF_RND
    o0 = x0 + ks2;
    o1 = x1 + k0 + 5u;
}
__device__ __forceinline__ unsigned tf_bits32(unsigned ka, unsigned kb, unsigned i) {
    unsigned o0, o1;
    threefry2x32(ka, kb, 0u, i, o0, o1);
    return o0 ^ o1;
}

__global__ void rng_bits_kernel() {
    int id = blockIdx.x * blockDim.x + threadIdx.x;
    if (id >= 3 * 1792) return;
    int l = id / 1792, m = id % 1792;
    unsigned ka, kb;
    threefry2x32(0u, 42u, 0u, (unsigned)l, ka, kb);
    unsigned k1a, k1b, k2a, k2b;
    threefry2x32(ka, kb, 0u, 0u, k1a, k1b);
    threefry2x32(ka, kb, 0u, 1u, k2a, k2b);
    unsigned ub = tf_bits32(k1a, k1b, (unsigned)m);
    float u = __uint_as_float((ub >> 9) | 0x3f800000u) - 1.0f;
    g_scale[l][m] = fmaxf(0.5f, u + 0.5f);
    unsigned ha, hb_, la, lb_;
    threefry2x32(k2a, k2b, 0u, 0u, ha, hb_);
    threefry2x32(k2a, k2b, 0u, 1u, la, lb_);
    unsigned hbits = tf_bits32(ha, hb_, (unsigned)m);
    unsigned lbits = tf_bits32(la, lb_, (unsigned)m);
    unsigned off = ((hbits % 13u) * 9u + (lbits % 13u)) % 13u;
    g_len[l][m] = 19 + (int)off;
}

__global__ void rng_scan_kernel() {
    int id = blockIdx.x * blockDim.x + threadIdx.x;
    if (id >= 3 * BATCH) return;
    int l = id / BATCH, b = id % BATCH;
    int cnt = 0, off = 0;
    for (int s = 0; s < 7; s++) {
        int m = b * 7 + s;
        float scale = g_scale[l][m];
        int   L     = g_len[l][m];
        float Lm1   = (float)(L - 1);
        float offf  = (float)off;
        for (int j = 0; j < 64; j++) {
            float is = (float)j / scale;
            float fl = floorf(is);
            if (fl < Lm1 && (fl + offf) < 191.0f) {
                if (cnt < TLEN) {
                    g_src[l][b][cnt] = (int)(fl + offf);
                    g_lam[l][b][cnt] = is - fl;
                }
                cnt++;
            }
        }
        off += L;
    }
    for (int t = cnt; t < TLEN; t++) g_src[l][b][t] = -1;
}

// ---------------- prep_x (layer 0 only): fp32 (B,Csrc,192) -> bf16 hi/lo (B,200,Cpad) ----------------
__global__ __launch_bounds__(256)
void prep_x_kernel(const float* __restrict__ src, int Csrc, int Cpad,
                   __nv_bfloat16* __restrict__ dhi, __nv_bfloat16* __restrict__ dlo) {
    __shared__ float s[32][65];
    int c0 = blockIdx.x * 32;
    int t0 = blockIdx.y * 64;
    int b  = blockIdx.z;
    int tid = threadIdx.x;
    for (int i = tid; i < 32 * 64; i += 256) {
        int ci = i >> 6, tt = i & 63;
        int tsrc = t0 + tt - 2;
        float v = 0.f;
        int c = c0 + ci;
        if (c < Csrc && tsrc >= 0 && tsrc < TLEN)
            v = src[((size_t)b * Csrc + c) * TLEN + tsrc];
        s[ci][tt] = v;
    }
    __syncthreads();
    for (int i = tid; i < 64 * 32; i += 256) {
        int tdl = i >> 5, cl = i & 31;
        int td = t0 + tdl;
        if (td < TPAD) {
            float f = s[cl][tdl];
            __nv_bfloat16 hi = __float2bfloat16(f);
            float lo = f - __bfloat162float(hi);
            size_t o = ((size_t)b * TPAD + td) * Cpad + c0 + cl;
            dhi[o] = hi;
            dlo[o] = __float2bfloat16(lo);
        }
    }
}

// ---------------- prep_w: fp32 (taps,Csrc,256) -> bf16 hi/lo (taps,Cpad,256) ----------------
__global__ __launch_bounds__(256)
void prep_w_kernel(const float* __restrict__ w, int taps, int Csrc, int Cpad) {
    int n = gridDim.x * blockDim.x;
    int total = taps * Cpad * 256;
    for (int i = blockIdx.x * blockDim.x + threadIdx.x; i < total; i += n) {
        int tap = i / (Cpad * 256);
        int rem = i % (Cpad * 256);
        int c = rem / 256, co = rem % 256;
        float v = (c < Csrc) ? w[((size_t)tap * Csrc + c) * 256 + co] : 0.f;
        __nv_bfloat16 hi = __float2bfloat16(v);
        float lo = v - __bfloat162float(hi);
        g_wb_hi[i] = hi;
        g_wb_lo[i] = __float2bfloat16(lo);
    }
}

// ---------------- prep_gw: gates weight (1,256,256) + bias ----------------
__global__ __launch_bounds__(256)
void prep_gw_kernel(const float* __restrict__ kf, const float* __restrict__ bf,
                    const float* __restrict__ kb, const float* __restrict__ bb) {
    int i = blockIdx.x * blockDim.x + threadIdx.x;
    if (i < 256 * 256) {
        int c = i / 256, nn = i % 256;
        float v = (nn < 128) ? kf[(size_t)c * 128 + nn] : kb[(size_t)c * 128 + (nn - 128)];
        __nv_bfloat16 hi = __float2bfloat16(v);
        float lo = v - __bfloat162float(hi);
        g_wb_hi[i] = hi;
        g_wb_lo[i] = __float2bfloat16(lo);
        if (i < 256) g_gbias[i] = (i < 128) ? bf[i] : bb[i - 128];
    }
}

// ---------------- legacy-HMMA GEMM, cp.async double-buffered ----------------
// A: bf16 activations (B, 200, Cpad), rows t (shift +2); W: (taps, Cpad, 256).
// Accumulates hi*hi + hi*lo(x) + lo(w)*hi in fp32 registers.
// Per-buffer smem: A tile 68x40 halfs (5440B) + B tile 5x32x136 halfs (43520B).
#define A_SZ 5440
#define B_SZ 43520
#define BUFSZ (A_SZ + B_SZ)

__global__ __launch_bounds__(256)
void mma_kernel(const __nv_bfloat16* __restrict__ Ahi, const __nv_bfloat16* __restrict__ Alo,
                const __nv_bfloat16* __restrict__ Whi, const __nv_bfloat16* __restrict__ Wlo,
                const float* __restrict__ bias, float* __restrict__ out,
                int Cpad, int tap_count, int tap_offset, int mode) {
    extern __shared__ char dsm[];
    const uint32_t sb = smem_u32(dsm);

    const int bn = blockIdx.x;      // n tile (128 wide)
    const int bm = blockIdx.y;      // m tile (64 wide)
    const int bb = blockIdx.z;      // batch
    const int tid  = threadIdx.x;
    const int wid  = tid >> 5;
    const int lane = tid & 31;
    const int warp_m = wid >> 2;    // 0..1
    const int warp_n = wid & 3;     // 0..3
    const int t0 = bm * 64;
    const int n0 = bn * 128;

    float acc[2][4][4];
#pragma unroll
    for (int i = 0; i < 2; i++)
#pragma unroll
        for (int j = 0; j < 4; j++)
#pragma unroll
            for (int k = 0; k < 4; k++) acc[i][j][k] = 0.f;

    const int kchunks = Cpad >> 5;
    const int total = 3 * kchunks;
    const int rs = Cpad >> 3;               // uint4 per activation row
    const int b_loads = tap_count * 512;

    // stage iteration 'it' into buffer it&1
    auto stage = [&](int it) {
        int sp = it / kchunks, kc = it % kchunks;
        const __nv_bfloat16* A = (sp == 1) ? Alo : Ahi;
        const __nv_bfloat16* W = (sp == 2) ? Wlo : Whi;
        uint32_t sa = sb + (uint32_t)(it & 1) * BUFSZ;
        uint32_t sw = sa + A_SZ;
        int k0 = kc * 32;
        const uint4* srcA = (const uint4*)(A + ((size_t)bb * TPAD + t0) * Cpad + k0);
        for (int i = tid; i < 272; i += 256) {
            int r = i >> 2, q = i & 3;
            CP16(sa + (uint32_t)(r * 80 + q * 16), srcA + (size_t)r * rs + q);
        }
        for (int i = tid; i < b_loads; i += 256) {
            int tp = i >> 9, r = (i >> 4) & 31, q = i & 15;
            const uint4* srcW = (const uint4*)(W + ((size_t)tp * Cpad + k0 + r) * 256 + n0);
            CP16(sw + (uint32_t)((tp * 32 + r) * 272 + q * 16), srcW + q);
        }
    };

    stage(0);
    CPCOMMIT();

    for (int it = 0; it < total; it++) {
        if (it + 1 < total) {
            stage(it + 1);
            CPCOMMIT();
            CPWAIT1();
        } else {
            CPWAIT0();
        }
        __syncthreads();

        uint32_t sa = sb + (uint32_t)(it & 1) * BUFSZ;
        uint32_t sw = sa + A_SZ;

        for (int tp = 0; tp < tap_count; tp++) {
            int cshift = tap_offset + tp;
#pragma unroll
            for (int kstep = 0; kstep < 2; kstep++) {
                unsigned a[2][4];
#pragma unroll
                for (int mt = 0; mt < 2; mt++) {
                    int row = warp_m * 32 + mt * 16 + cshift + (lane & 15);
                    int col = kstep * 16 + ((lane >> 4) * 8);
                    uint32_t addr = sa + (uint32_t)(row * 80 + col * 2);
                    asm volatile("ldmatrix.sync.aligned.m8n8.x4.shared.b16 {%0,%1,%2,%3}, [%4];"
                                 : "=r"(a[mt][0]), "=r"(a[mt][1]), "=r"(a[mt][2]), "=r"(a[mt][3])
                                 : "r"(addr));
                }
                unsigned bfr[4][2];
#pragma unroll
                for (int np = 0; np < 2; np++) {
                    int row = kstep * 16 + (lane & 15);
                    int col = warp_n * 32 + np * 16 + ((lane >= 16) ? 8 : 0);
                    uint32_t addr = sw + (uint32_t)((tp * 32 + row) * 272 + col * 2);
                    unsigned r0, r1, r2, r3;
                    asm volatile("ldmatrix.sync.aligned.m8n8.x4.trans.shared.b16 {%0,%1,%2,%3}, [%4];"
                                 : "=r"(r0), "=r"(r1), "=r"(r2), "=r"(r3)
                                 : "r"(addr));
                    bfr[np * 2 + 0][0] = r0; bfr[np * 2 + 0][1] = r1;
                    bfr[np * 2 + 1][0] = r2; bfr[np * 2 + 1][1] = r3;
                }
#pragma unroll
                for (int mt = 0; mt < 2; mt++)
#pragma unroll
                    for (int nt = 0; nt < 4; nt++) {
                        asm volatile(
                            "mma.sync.aligned.m16n8k16.row.col.f32.bf16.bf16.f32 "
                            "{%0,%1,%2,%3},{%4,%5,%6,%7},{%8,%9},{%0,%1,%2,%3};"
                            : "+f"(acc[mt][nt][0]), "+f"(acc[mt][nt][1]),
                              "+f"(acc[mt][nt][2]), "+f"(acc[mt][nt][3])
                            : "r"(a[mt][0]), "r"(a[mt][1]), "r"(a[mt][2]), "r"(a[mt][3]),
                              "r"(bfr[nt][0]), "r"(bfr[nt][1]));
                    }
            }
        }
        __syncthreads();
    }

    // epilogue
    int gid = lane >> 2, tig = lane & 3;
#pragma unroll
    for (int mt = 0; mt < 2; mt++) {
#pragma unroll
        for (int nt = 0; nt < 4; nt++) {
            int t  = t0 + warp_m * 32 + mt * 16 + gid;
            int co = n0 + warp_n * 32 + nt * 8 + tig * 2;
            float bv0 = bias[co], bv1 = bias[co + 1];
            if (mode == 0) {
                float* yp0 = out + ((size_t)bb * 256 + co) * TLEN;
                float* yp1 = yp0 + TLEN;
                yp0[t]     = acc[mt][nt][0] + bv0;
                yp1[t]     = acc[mt][nt][1] + bv1;
                yp0[t + 8] = acc[mt][nt][2] + bv0;
                yp1[t + 8] = acc[mt][nt][3] + bv1;
            } else {
                int dir0 = co >> 7, g0 = co & 127;
                int dir1 = (co + 1) >> 7, g1 = (co + 1) & 127;
                size_t r0 = ((size_t)(dir0 * BATCH + bb) * TLEN + t) * NGATE + g0;
                size_t r1 = ((size_t)(dir1 * BATCH + bb) * TLEN + t) * NGATE + g1;
                out[r0] = acc[mt][nt][0] + bv0;
                out[r1] = acc[mt][nt][1] + bv1;
                size_t r2 = ((size_t)(dir0 * BATCH + bb) * TLEN + t + 8) * NGATE + g0;
                size_t r3 = ((size_t)(dir1 * BATCH + bb) * TLEN + t + 8) * NGATE + g1;
                out[r2] = acc[mt][nt][2] + bv0;
                out[r3] = acc[mt][nt][3] + bv1;
            }
        }
    }
}

// ---------------- per-sample mean/istd over (C,T), fp32 ----------------
__global__ __launch_bounds__(256)
void stats_kernel(const float* __restrict__ y) {
    int b = blockIdx.x;
    const float4* p = (const float4*)(y + (size_t)b * CENC * TLEN);
    float s0 = 0.f, s1 = 0.f, q0 = 0.f, q1 = 0.f;
    for (int i = threadIdx.x; i < CENC * TLEN / 4; i += 256) {
        float4 v = p[i];
        s0 += v.x + v.y;
        s1 += v.z + v.w;
        q0 = fmaf(v.x, v.x, fmaf(v.y, v.y, q0));
        q1 = fmaf(v.z, v.z, fmaf(v.w, v.w, q1));
    }
    float s = s0 + s1, q = q0 + q1;
    __shared__ float sh[256], sh2[256];
    sh[threadIdx.x] = s; sh2[threadIdx.x] = q;
    __syncthreads();
    for (int k = 128; k > 0; k >>= 1) {
        if (threadIdx.x < k) { sh[threadIdx.x] += sh[threadIdx.x + k]; sh2[threadIdx.x] += sh2[threadIdx.x + k]; }
        __syncthreads();
    }
    if (threadIdx.x == 0) {
        float mm = sh[0] / (float)(CENC * TLEN);
        float var = sh2[0] / (float)(CENC * TLEN) - mm * mm;
        g_mean[b] = mm;
        g_istd[b] = rsqrtf(var + 1e-5f);
    }
}

// ---------------- fused GN + ReLU + interp gather + bf16 hi/lo transpose ----------------
// reads y (B,C,T) fp32; writes ax hi/lo (B, 200, 256), row t+2, col c. Also zero-pads rows.
__global__ __launch_bounds__(256)
void gather_fuse_kernel(const float* __restrict__ y,
                        __nv_bfloat16* __restrict__ dhi, __nv_bfloat16* __restrict__ dlo,
                        const float* __restrict__ gamma, const float* __restrict__ beta,
                        int layer) {
    __shared__ float s[TLEN][33];
    int b = blockIdx.x, cz = blockIdx.y;
    int c0 = cz * 32;
    float mean = g_mean[b], istd = g_istd[b];
    int tid = threadIdx.x;

    for (int i = tid; i < 32 * TLEN; i += 256) {
        int ci = i / TLEN;
        int t = i % TLEN;
        int src = g_src[layer][b][t];
        float v = 0.f;
        if (src >= 0) {
            float lam = g_lam[layer][b][t];
            const float* yr = y + ((size_t)b * CENC + c0 + ci) * TLEN;
            float r0 = fmaxf((yr[src]     - mean) * istd * gamma[src]     + beta[src],     0.f);
            float r1 = fmaxf((yr[src + 1] - mean) * istd * gamma[src + 1] + beta[src + 1], 0.f);
            v = (1.f - lam) * r0 + lam * r1;
        }
        s[t][ci] = v;
    }
    __syncthreads();

    // transposed write: rows t+2, cols c
    for (int i = tid; i < TLEN * 32; i += 256) {
        int t = i >> 5, ci = i & 31;
        float f = s[t][ci];
        __nv_bfloat16 hi = __float2bfloat16(f);
        float lo = f - __bfloat162float(hi);
        size_t o = ((size_t)b * TPAD + t + 2) * CENC + c0 + ci;
        dhi[o] = hi;
        dlo[o] = __float2bfloat16(lo);
    }
    // zero pad rows {0,1,194..199}
    if (tid < 256) {
        const int padrows[8] = {0, 1, 194, 195, 196, 197, 198, 199};
        int pr = padrows[tid >> 5], ci = tid & 31;
        size_t o = ((size_t)b * TPAD + pr) * CENC + c0 + ci;
        dhi[o] = __float2bfloat16(0.f);
        dlo[o] = __float2bfloat16(0.f);
    }
}

// ---------------- LSTM recurrence ----------------
__device__ __forceinline__ float sigm(float x) { return 1.f / (1.f + expf(-x)); }

__global__ __launch_bounds__(256)
void lstm_kernel(const float* __restrict__ pre,
                 const float* __restrict__ rf, const float* __restrict__ rb,
                 float* __restrict__ out) {
    __shared__ __align__(16) float Rs[32][128];
    int dir = blockIdx.y;
    const float* R = dir ? rb : rf;
    for (int i = threadIdx.x; i < 32 * 128; i += 256) Rs[i >> 7][i & 127] = R[i];
    __syncthreads();

    int warp = threadIdx.x >> 5, lane = threadIdx.x & 31;
    int b = blockIdx.x * 8 + warp;
    float h = 0.f, c = 0.f;
    const float* preb = pre + (((size_t)dir * BATCH + b) * TLEN) * NGATE;

    for (int s = 0; s < TLEN; s++) {
        int t = dir ? (TLEN - 1 - s) : s;
        const float* p = preb + (size_t)t * NGATE;
        float zi = p[lane], zf = p[32 + lane], zg = p[64 + lane], zo = p[96 + lane];
#pragma unroll
        for (int j = 0; j < 32; j++) {
            float hj = __shfl_sync(0xffffffffu, h, j);
            zi += hj * Rs[j][lane];
            zf += hj * Rs[j][32 + lane];
            zg += hj * Rs[j][64 + lane];
            zo += hj * Rs[j][96 + lane];
        }
        c = sigm(zf) * c + sigm(zi) * tanhf(zg);
        h = sigm(zo) * tanhf(c);
        out[((size_t)b * TLEN + t) * 64 + dir * 32 + lane] = h;
    }
}

// ---------------- launch ----------------
extern "C" void kernel_launch(void* const* d_in, const int* in_sizes, int n_in,
                              void* d_out, int out_size) {
    const float* x   = (const float*)d_in[0];
    const float* w0  = (const float*)d_in[1];
    const float* b0  = (const float*)d_in[2];
    const float* w1  = (const float*)d_in[3];
    const float* b1  = (const float*)d_in[4];
    const float* w2  = (const float*)d_in[5];
    const float* b2  = (const float*)d_in[6];
    const float* g0  = (const float*)d_in[7];
    const float* be0 = (const float*)d_in[8];
    const float* g1  = (const float*)d_in[9];
    const float* be1 = (const float*)d_in[10];
    const float* g2  = (const float*)d_in[11];
    const float* be2 = (const float*)d_in[12];
    const float* kf  = (const float*)d_in[13];
    const float* rf  = (const float*)d_in[14];
    const float* bf  = (const float*)d_in[15];
    const float* kb  = (const float*)d_in[16];
    const float* rb  = (const float*)d_in[17];
    const float* bb  = (const float*)d_in[18];

    float *bufy, *pre, *gbias;
    __nv_bfloat16 *axh, *axl, *wbh, *wbl;
    cudaGetSymbolAddress((void**)&bufy, g_bufy);
    cudaGetSymbolAddress((void**)&pre,  g_pre);
    cudaGetSymbolAddress((void**)&gbias, g_gbias);
    cudaGetSymbolAddress((void**)&axh, g_ax_hi);
    cudaGetSymbolAddress((void**)&axl, g_ax_lo);
    cudaGetSymbolAddress((void**)&wbh, g_wb_hi);
    cudaGetSymbolAddress((void**)&wbl, g_wb_lo);

    const int SMEM_MMA = 2 * BUFSZ;   // 97920
    cudaFuncSetAttribute(mma_kernel, cudaFuncAttributeMaxDynamicSharedMemorySize, SMEM_MMA);

    rng_bits_kernel<<<21, 256>>>();
    rng_scan_kernel<<<3, 256>>>();

    dim3 gmma(2, 3, BATCH);
    dim3 ggath(BATCH, 8);

    // layer 0 (Csrc=257, Cpad=320)
    prep_w_kernel<<<320, 256>>>(w0, 5, 257, 320);
    prep_x_kernel<<<dim3(10, 4, BATCH), 256>>>(x, 257, 320, axh, axl);
    mma_kernel<<<gmma, 256, SMEM_MMA>>>(axh, axl, wbh, wbl, b0, bufy, 320, 5, 0, 0);
    stats_kernel<<<BATCH, 256>>>(bufy);
    gather_fuse_kernel<<<ggath, 256>>>(bufy, axh, axl, g0, be0, 0);
    // layer 1 (Cpad=256)
    prep_w_kernel<<<256, 256>>>(w1, 5, 256, 256);
    mma_kernel<<<gmma, 256, SMEM_MMA>>>(axh, axl, wbh, wbl, b1, bufy, 256, 5, 0, 0);
    stats_kernel<<<BATCH, 256>>>(bufy);
    gather_fuse_kernel<<<ggath, 256>>>(bufy, axh, axl, g1, be1, 1);
    // layer 2
    prep_w_kernel<<<256, 256>>>(w2, 5, 256, 256);
    mma_kernel<<<gmma, 256, SMEM_MMA>>>(axh, axl, wbh, wbl, b2, bufy, 256, 5, 0, 0);
    stats_kernel<<<BATCH, 256>>>(bufy);
    gather_fuse_kernel<<<ggath, 256>>>(bufy, axh, axl, g2, be2, 2);

    // gates GEMM: taps=1 at offset 2 (time t), mode 1; input = layer2 gather output
    prep_gw_kernel<<<256, 256>>>(kf, bf, kb, bb);
    mma_kernel<<<gmma, 256, SMEM_MMA>>>(axh, axl, wbh, wbl, gbias, pre, 256, 1, 2, 1);

    lstm_kernel<<<dim3(32, 2), 256>>>(pre, rf, rb, (float*)d_out);
}

// round 8
// speedup vs baseline: 2.7755x; 1.2624x over previous
#include <cuda_runtime.h>
#include <cuda_fp16.h>
#include <math.h>
#include <stdint.h>

#define BATCH 256
#define TLEN  192
#define CENC  256
#define NGATE 128
#define NECK  32
#define TPAD  200
#define CPAD_MAX 320

// ---------------- scratch ----------------
__device__ float g_bufy[(size_t)BATCH * CENC * TLEN];            // conv output (B,C,T)
__device__ float g_pre [(size_t)2 * BATCH * TLEN * NGATE];       // lstm pre-gates
__device__ __half g_ax_hi[(size_t)BATCH * TPAD * CPAD_MAX];
__device__ __half g_ax_lo[(size_t)BATCH * TPAD * CPAD_MAX];
__device__ __half g_wb[(size_t)5 * CPAD_MAX * 256];              // (tap, c, co) fp16
__device__ float g_gbias[256];
__device__ float g_scale[3][1792];
__device__ int   g_len  [3][1792];
__device__ int   g_src  [3][BATCH][TLEN];
__device__ float g_lam  [3][BATCH][TLEN];
__device__ float g_mean [BATCH];
__device__ float g_istd [BATCH];

// ---------------- cp.async helpers ----------------
#define CP16(dst, src) \
    asm volatile("cp.async.cg.shared.global [%0], [%1], 16;" :: "r"(dst), "l"(src))
#define CPCOMMIT() asm volatile("cp.async.commit_group;")
#define CPWAIT1()  asm volatile("cp.async.wait_group 1;")
#define CPWAIT0()  asm volatile("cp.async.wait_group 0;")

__device__ __forceinline__ uint32_t smem_u32(const void* p) {
    uint32_t a;
    asm("{ .reg .u64 t; cvta.to.shared.u64 t, %1; cvt.u32.u64 %0, t; }" : "=r"(a) : "l"(p));
    return a;
}

// ---------------- threefry2x32 (bit-exact JAX PRNG) ----------------
__device__ __forceinline__ unsigned tf_rotl(unsigned v, int r) {
    return (v << r) | (v >> (32 - r));
}
__device__ __forceinline__ void threefry2x32(unsigned k0, unsigned k1,
                                             unsigned x0, unsigned x1,
                                             unsigned& o0, unsigned& o1) {
    unsigned ks2 = k0 ^ k1 ^ 0x1BD11BDAu;
    x0 += k0; x1 += k1;
#define TF_RND(r) { x0 += x1; x1 = tf_rotl(x1, r); x1 ^= x0; }
    TF_RND(13) TF_RND(15) TF_RND(26) TF_RND(6)
    x0 += k1;  x1 += ks2 + 1u;
    TF_RND(17) TF_RND(29) TF_RND(16) TF_RND(24)
    x0 += ks2; x1 += k0 + 2u;
    TF_RND(13) TF_RND(15) TF_RND(26) TF_RND(6)
    x0 += k0;  x1 += k1 + 3u;
    TF_RND(17) TF_RND(29) TF_RND(16) TF_RND(24)
    x0 += k1;  x1 += ks2 + 4u;
    TF_RND(13) TF_RND(15) TF_RND(26) TF_RND(6)
#undef TF_RND
    o0 = x0 + ks2;
    o1 = x1 + k0 + 5u;
}
__device__ __forceinline__ unsigned tf_bits32(unsigned ka, unsigned kb, unsigned i) {
    unsigned o0, o1;
    threefry2x32(ka, kb, 0u, i, o0, o1);
    return o0 ^ o1;
}

__global__ void rng_bits_kernel() {
    int id = blockIdx.x * blockDim.x + threadIdx.x;
    if (id >= 3 * 1792) return;
    int l = id / 1792, m = id % 1792;
    unsigned ka, kb;
    threefry2x32(0u, 42u, 0u, (unsigned)l, ka, kb);
    unsigned k1a, k1b, k2a, k2b;
    threefry2x32(ka, kb, 0u, 0u, k1a, k1b);
    threefry2x32(ka, kb, 0u, 1u, k2a, k2b);
    unsigned ub = tf_bits32(k1a, k1b, (unsigned)m);
    float u = __uint_as_float((ub >> 9) | 0x3f800000u) - 1.0f;
    g_scale[l][m] = fmaxf(0.5f, u + 0.5f);
    unsigned ha, hb_, la, lb_;
    threefry2x32(k2a, k2b, 0u, 0u, ha, hb_);
    threefry2x32(k2a, k2b, 0u, 1u, la, lb_);
    unsigned hbits = tf_bits32(ha, hb_, (unsigned)m);
    unsigned lbits = tf_bits32(la, lb_, (unsigned)m);
    unsigned off = ((hbits % 13u) * 9u + (lbits % 13u)) % 13u;
    g_len[l][m] = 19 + (int)off;
}

__global__ void rng_scan_kernel() {
    int id = blockIdx.x * blockDim.x + threadIdx.x;
    if (id >= 3 * BATCH) return;
    int l = id / BATCH, b = id % BATCH;
    int cnt = 0, off = 0;
    for (int s = 0; s < 7; s++) {
        int m = b * 7 + s;
        float scale = g_scale[l][m];
        int   L     = g_len[l][m];
        float Lm1   = (float)(L - 1);
        float offf  = (float)off;
        for (int j = 0; j < 64; j++) {
            float is = (float)j / scale;
            float fl = floorf(is);
            if (fl < Lm1 && (fl + offf) < 191.0f) {
                if (cnt < TLEN) {
                    g_src[l][b][cnt] = (int)(fl + offf);
                    g_lam[l][b][cnt] = is - fl;
                }
                cnt++;
            }
        }
        off += L;
    }
    for (int t = cnt; t < TLEN; t++) g_src[l][b][t] = -1;
}

// ---------------- prep_x (layer 0 only): fp32 (B,Csrc,192) -> fp16 hi/lo (B,200,Cpad) ----------------
__global__ __launch_bounds__(256)
void prep_x_kernel(const float* __restrict__ src, int Csrc, int Cpad,
                   __half* __restrict__ dhi, __half* __restrict__ dlo) {
    __shared__ float s[32][65];
    int c0 = blockIdx.x * 32;
    int t0 = blockIdx.y * 64;
    int b  = blockIdx.z;
    int tid = threadIdx.x;
    for (int i = tid; i < 32 * 64; i += 256) {
        int ci = i >> 6, tt = i & 63;
        int tsrc = t0 + tt - 2;
        float v = 0.f;
        int c = c0 + ci;
        if (c < Csrc && tsrc >= 0 && tsrc < TLEN)
            v = src[((size_t)b * Csrc + c) * TLEN + tsrc];
        s[ci][tt] = v;
    }
    __syncthreads();
    for (int i = tid; i < 64 * 32; i += 256) {
        int tdl = i >> 5, cl = i & 31;
        int td = t0 + tdl;
        if (td < TPAD) {
            float f = s[cl][tdl];
            __half hi = __float2half_rn(f);
            float lo = f - __half2float(hi);
            size_t o = ((size_t)b * TPAD + td) * Cpad + c0 + cl;
            dhi[o] = hi;
            dlo[o] = __float2half_rn(lo);
        }
    }
}

// ---------------- prep_w: fp32 (taps,Csrc,256) -> fp16 (taps,Cpad,256) ----------------
__global__ __launch_bounds__(256)
void prep_w_kernel(const float* __restrict__ w, int taps, int Csrc, int Cpad) {
    int n = gridDim.x * blockDim.x;
    int total = taps * Cpad * 256;
    for (int i = blockIdx.x * blockDim.x + threadIdx.x; i < total; i += n) {
        int tap = i / (Cpad * 256);
        int rem = i % (Cpad * 256);
        int c = rem / 256, co = rem % 256;
        float v = (c < Csrc) ? w[((size_t)tap * Csrc + c) * 256 + co] : 0.f;
        g_wb[i] = __float2half_rn(v);
    }
}

// ---------------- prep_gw: gates weight (1,256,256) + bias ----------------
__global__ __launch_bounds__(256)
void prep_gw_kernel(const float* __restrict__ kf, const float* __restrict__ bf,
                    const float* __restrict__ kb, const float* __restrict__ bb) {
    int i = blockIdx.x * blockDim.x + threadIdx.x;
    if (i < 256 * 256) {
        int c = i / 256, nn = i % 256;
        float v = (nn < 128) ? kf[(size_t)c * 128 + nn] : kb[(size_t)c * 128 + (nn - 128)];
        g_wb[i] = __float2half_rn(v);
        if (i < 256) g_gbias[i] = (i < 128) ? bf[i] : bb[i - 128];
    }
}

// ---------------- legacy-HMMA GEMM, cp.async double-buffered, fp16 2-split ----------------
// A: fp16 activations (B, 200, Cpad) rows t (+2 shift); W: fp16 (taps, Cpad, 256).
// Accumulates hi*w + lo*w in fp32.
#define A_SZ 5440
#define B_SZ 43520
#define BUFSZ (A_SZ + B_SZ)

__global__ __launch_bounds__(256)
void mma_kernel(const __half* __restrict__ Ahi, const __half* __restrict__ Alo,
                const __half* __restrict__ Wgt,
                const float* __restrict__ bias, float* __restrict__ out,
                int Cpad, int tap_count, int tap_offset, int mode) {
    extern __shared__ char dsm[];
    const uint32_t sb = smem_u32(dsm);

    const int bn = blockIdx.x;      // n tile (128 wide)
    const int bm = blockIdx.y;      // m tile (64 wide)
    const int bb = blockIdx.z;      // batch
    const int tid  = threadIdx.x;
    const int wid  = tid >> 5;
    const int lane = tid & 31;
    const int warp_m = wid >> 2;    // 0..1
    const int warp_n = wid & 3;     // 0..3
    const int t0 = bm * 64;
    const int n0 = bn * 128;

    float acc[2][4][4];
#pragma unroll
    for (int i = 0; i < 2; i++)
#pragma unroll
        for (int j = 0; j < 4; j++)
#pragma unroll
            for (int k = 0; k < 4; k++) acc[i][j][k] = 0.f;

    const int kchunks = Cpad >> 5;
    const int total = 2 * kchunks;
    const int rs = Cpad >> 3;               // uint4 per activation row
    const int b_loads = tap_count * 512;

    // stage iteration 'it' into buffer it&1
    auto stage = [&](int it) {
        int sp = it / kchunks, kc = it % kchunks;
        const __half* A = sp ? Alo : Ahi;
        uint32_t sa = sb + (uint32_t)(it & 1) * BUFSZ;
        uint32_t sw = sa + A_SZ;
        int k0 = kc * 32;
        const uint4* srcA = (const uint4*)(A + ((size_t)bb * TPAD + t0) * Cpad + k0);
        for (int i = tid; i < 272; i += 256) {
            int r = i >> 2, q = i & 3;
            CP16(sa + (uint32_t)(r * 80 + q * 16), srcA + (size_t)r * rs + q);
        }
        for (int i = tid; i < b_loads; i += 256) {
            int tp = i >> 9, r = (i >> 4) & 31, q = i & 15;
            const uint4* srcW = (const uint4*)(Wgt + ((size_t)tp * Cpad + k0 + r) * 256 + n0);
            CP16(sw + (uint32_t)((tp * 32 + r) * 272 + q * 16), srcW + q);
        }
    };

    stage(0);
    CPCOMMIT();

    for (int it = 0; it < total; it++) {
        if (it + 1 < total) {
            stage(it + 1);
            CPCOMMIT();
            CPWAIT1();
        } else {
            CPWAIT0();
        }
        __syncthreads();

        uint32_t sa = sb + (uint32_t)(it & 1) * BUFSZ;
        uint32_t sw = sa + A_SZ;

        for (int tp = 0; tp < tap_count; tp++) {
            int cshift = tap_offset + tp;
#pragma unroll
            for (int kstep = 0; kstep < 2; kstep++) {
                unsigned a[2][4];
#pragma unroll
                for (int mt = 0; mt < 2; mt++) {
                    int row = warp_m * 32 + mt * 16 + cshift + (lane & 15);
                    int col = kstep * 16 + ((lane >> 4) * 8);
                    uint32_t addr = sa + (uint32_t)(row * 80 + col * 2);
                    asm volatile("ldmatrix.sync.aligned.m8n8.x4.shared.b16 {%0,%1,%2,%3}, [%4];"
                                 : "=r"(a[mt][0]), "=r"(a[mt][1]), "=r"(a[mt][2]), "=r"(a[mt][3])
                                 : "r"(addr));
                }
                unsigned bfr[4][2];
#pragma unroll
                for (int np = 0; np < 2; np++) {
                    int row = kstep * 16 + (lane & 15);
                    int col = warp_n * 32 + np * 16 + ((lane >= 16) ? 8 : 0);
                    uint32_t addr = sw + (uint32_t)((tp * 32 + row) * 272 + col * 2);
                    unsigned r0, r1, r2, r3;
                    asm volatile("ldmatrix.sync.aligned.m8n8.x4.trans.shared.b16 {%0,%1,%2,%3}, [%4];"
                                 : "=r"(r0), "=r"(r1), "=r"(r2), "=r"(r3)
                                 : "r"(addr));
                    bfr[np * 2 + 0][0] = r0; bfr[np * 2 + 0][1] = r1;
                    bfr[np * 2 + 1][0] = r2; bfr[np * 2 + 1][1] = r3;
                }
#pragma unroll
                for (int mt = 0; mt < 2; mt++)
#pragma unroll
                    for (int nt = 0; nt < 4; nt++) {
                        asm volatile(
                            "mma.sync.aligned.m16n8k16.row.col.f32.f16.f16.f32 "
                            "{%0,%1,%2,%3},{%4,%5,%6,%7},{%8,%9},{%0,%1,%2,%3};"
                            : "+f"(acc[mt][nt][0]), "+f"(acc[mt][nt][1]),
                              "+f"(acc[mt][nt][2]), "+f"(acc[mt][nt][3])
                            : "r"(a[mt][0]), "r"(a[mt][1]), "r"(a[mt][2]), "r"(a[mt][3]),
                              "r"(bfr[nt][0]), "r"(bfr[nt][1]));
                    }
            }
        }
        __syncthreads();
    }

    // epilogue
    int gid = lane >> 2, tig = lane & 3;
#pragma unroll
    for (int mt = 0; mt < 2; mt++) {
#pragma unroll
        for (int nt = 0; nt < 4; nt++) {
            int t  = t0 + warp_m * 32 + mt * 16 + gid;
            int co = n0 + warp_n * 32 + nt * 8 + tig * 2;
            float bv0 = bias[co], bv1 = bias[co + 1];
            if (mode == 0) {
                float* yp0 = out + ((size_t)bb * 256 + co) * TLEN;
                float* yp1 = yp0 + TLEN;
                yp0[t]     = acc[mt][nt][0] + bv0;
                yp1[t]     = acc[mt][nt][1] + bv1;
                yp0[t + 8] = acc[mt][nt][2] + bv0;
                yp1[t + 8] = acc[mt][nt][3] + bv1;
            } else {
                int dir0 = co >> 7, g0 = co & 127;
                int dir1 = (co + 1) >> 7, g1 = (co + 1) & 127;
                size_t r0 = ((size_t)(dir0 * BATCH + bb) * TLEN + t) * NGATE + g0;
                size_t r1 = ((size_t)(dir1 * BATCH + bb) * TLEN + t) * NGATE + g1;
                out[r0] = acc[mt][nt][0] + bv0;
                out[r1] = acc[mt][nt][1] + bv1;
                size_t r2 = ((size_t)(dir0 * BATCH + bb) * TLEN + t + 8) * NGATE + g0;
                size_t r3 = ((size_t)(dir1 * BATCH + bb) * TLEN + t + 8) * NGATE + g1;
                out[r2] = acc[mt][nt][2] + bv0;
                out[r3] = acc[mt][nt][3] + bv1;
            }
        }
    }
}

// ---------------- per-sample mean/istd over (C,T), fp32 ----------------
__global__ __launch_bounds__(256)
void stats_kernel(const float* __restrict__ y) {
    int b = blockIdx.x;
    const float4* p = (const float4*)(y + (size_t)b * CENC * TLEN);
    float s0 = 0.f, s1 = 0.f, q0 = 0.f, q1 = 0.f;
    for (int i = threadIdx.x; i < CENC * TLEN / 4; i += 256) {
        float4 v = p[i];
        s0 += v.x + v.y;
        s1 += v.z + v.w;
        q0 = fmaf(v.x, v.x, fmaf(v.y, v.y, q0));
        q1 = fmaf(v.z, v.z, fmaf(v.w, v.w, q1));
    }
    float s = s0 + s1, q = q0 + q1;
    __shared__ float sh[256], sh2[256];
    sh[threadIdx.x] = s; sh2[threadIdx.x] = q;
    __syncthreads();
    for (int k = 128; k > 0; k >>= 1) {
        if (threadIdx.x < k) { sh[threadIdx.x] += sh[threadIdx.x + k]; sh2[threadIdx.x] += sh2[threadIdx.x + k]; }
        __syncthreads();
    }
    if (threadIdx.x == 0) {
        float mm = sh[0] / (float)(CENC * TLEN);
        float var = sh2[0] / (float)(CENC * TLEN) - mm * mm;
        g_mean[b] = mm;
        g_istd[b] = rsqrtf(var + 1e-5f);
    }
}

// ---------------- fused GN + ReLU + interp gather + fp16 hi/lo transpose ----------------
__global__ __launch_bounds__(256)
void gather_fuse_kernel(const float* __restrict__ y,
                        __half* __restrict__ dhi, __half* __restrict__ dlo,
                        const float* __restrict__ gamma, const float* __restrict__ beta,
                        int layer) {
    __shared__ float s[TLEN][33];
    int b = blockIdx.x, cz = blockIdx.y;
    int c0 = cz * 32;
    float mean = g_mean[b], istd = g_istd[b];
    int tid = threadIdx.x;

    for (int i = tid; i < 32 * TLEN; i += 256) {
        int ci = i / TLEN;
        int t = i % TLEN;
        int src = g_src[layer][b][t];
        float v = 0.f;
        if (src >= 0) {
            float lam = g_lam[layer][b][t];
            const float* yr = y + ((size_t)b * CENC + c0 + ci) * TLEN;
            float r0 = fmaxf((yr[src]     - mean) * istd * gamma[src]     + beta[src],     0.f);
            float r1 = fmaxf((yr[src + 1] - mean) * istd * gamma[src + 1] + beta[src + 1], 0.f);
            v = (1.f - lam) * r0 + lam * r1;
        }
        s[t][ci] = v;
    }
    __syncthreads();

    for (int i = tid; i < TLEN * 32; i += 256) {
        int t = i >> 5, ci = i & 31;
        float f = s[t][ci];
        __half hi = __float2half_rn(f);
        float lo = f - __half2float(hi);
        size_t o = ((size_t)b * TPAD + t + 2) * CENC + c0 + ci;
        dhi[o] = hi;
        dlo[o] = __float2half_rn(lo);
    }
    if (tid < 256) {
        const int padrows[8] = {0, 1, 194, 195, 196, 197, 198, 199};
        int pr = padrows[tid >> 5], ci = tid & 31;
        size_t o = ((size_t)b * TPAD + pr) * CENC + c0 + ci;
        dhi[o] = __float2half_rn(0.f);
        dlo[o] = __float2half_rn(0.f);
    }
}

// ---------------- LSTM recurrence ----------------
__device__ __forceinline__ float sigm(float x) { return 1.f / (1.f + expf(-x)); }

__global__ __launch_bounds__(256)
void lstm_kernel(const float* __restrict__ pre,
                 const float* __restrict__ rf, const float* __restrict__ rb,
                 float* __restrict__ out) {
    __shared__ __align__(16) float Rs[32][128];
    int dir = blockIdx.y;
    const float* R = dir ? rb : rf;
    for (int i = threadIdx.x; i < 32 * 128; i += 256) Rs[i >> 7][i & 127] = R[i];
    __syncthreads();

    int warp = threadIdx.x >> 5, lane = threadIdx.x & 31;
    int b = blockIdx.x * 8 + warp;
    float h = 0.f, c = 0.f;
    const float* preb = pre + (((size_t)dir * BATCH + b) * TLEN) * NGATE;

    for (int s = 0; s < TLEN; s++) {
        int t = dir ? (TLEN - 1 - s) : s;
        const float* p = preb + (size_t)t * NGATE;
        float zi = p[lane], zf = p[32 + lane], zg = p[64 + lane], zo = p[96 + lane];
#pragma unroll
        for (int j = 0; j < 32; j++) {
            float hj = __shfl_sync(0xffffffffu, h, j);
            zi += hj * Rs[j][lane];
            zf += hj * Rs[j][32 + lane];
            zg += hj * Rs[j][64 + lane];
            zo += hj * Rs[j][96 + lane];
        }
        c = sigm(zf) * c + sigm(zi) * tanhf(zg);
        h = sigm(zo) * tanhf(c);
        out[((size_t)b * TLEN + t) * 64 + dir * 32 + lane] = h;
    }
}

// ---------------- launch ----------------
extern "C" void kernel_launch(void* const* d_in, const int* in_sizes, int n_in,
                              void* d_out, int out_size) {
    const float* x   = (const float*)d_in[0];
    const float* w0  = (const float*)d_in[1];
    const float* b0  = (const float*)d_in[2];
    const float* w1  = (const float*)d_in[3];
    const float* b1  = (const float*)d_in[4];
    const float* w2  = (const float*)d_in[5];
    const float* b2  = (const float*)d_in[6];
    const float* g0  = (const float*)d_in[7];
    const float* be0 = (const float*)d_in[8];
    const float* g1  = (const float*)d_in[9];
    const float* be1 = (const float*)d_in[10];
    const float* g2  = (const float*)d_in[11];
    const float* be2 = (const float*)d_in[12];
    const float* kf  = (const float*)d_in[13];
    const float* rf  = (const float*)d_in[14];
    const float* bf  = (const float*)d_in[15];
    const float* kb  = (const float*)d_in[16];
    const float* rb  = (const float*)d_in[17];
    const float* bb  = (const float*)d_in[18];

    float *bufy, *pre, *gbias;
    __half *axh, *axl, *wb;
    cudaGetSymbolAddress((void**)&bufy, g_bufy);
    cudaGetSymbolAddress((void**)&pre,  g_pre);
    cudaGetSymbolAddress((void**)&gbias, g_gbias);
    cudaGetSymbolAddress((void**)&axh, g_ax_hi);
    cudaGetSymbolAddress((void**)&axl, g_ax_lo);
    cudaGetSymbolAddress((void**)&wb,  g_wb);

    const int SMEM_MMA = 2 * BUFSZ;   // 97920
    cudaFuncSetAttribute(mma_kernel, cudaFuncAttributeMaxDynamicSharedMemorySize, SMEM_MMA);

    rng_bits_kernel<<<21, 256>>>();
    rng_scan_kernel<<<3, 256>>>();

    dim3 gmma(2, 3, BATCH);
    dim3 ggath(BATCH, 8);

    // layer 0 (Csrc=257, Cpad=320)
    prep_w_kernel<<<320, 256>>>(w0, 5, 257, 320);
    prep_x_kernel<<<dim3(10, 4, BATCH), 256>>>(x, 257, 320, axh, axl);
    mma_kernel<<<gmma, 256, SMEM_MMA>>>(axh, axl, wb, b0, bufy, 320, 5, 0, 0);
    stats_kernel<<<BATCH, 256>>>(bufy);
    gather_fuse_kernel<<<ggath, 256>>>(bufy, axh, axl, g0, be0, 0);
    // layer 1 (Cpad=256)
    prep_w_kernel<<<256, 256>>>(w1, 5, 256, 256);
    mma_kernel<<<gmma, 256, SMEM_MMA>>>(axh, axl, wb, b1, bufy, 256, 5, 0, 0);
    stats_kernel<<<BATCH, 256>>>(bufy);
    gather_fuse_kernel<<<ggath, 256>>>(bufy, axh, axl, g1, be1, 1);
    // layer 2
    prep_w_kernel<<<256, 256>>>(w2, 5, 256, 256);
    mma_kernel<<<gmma, 256, SMEM_MMA>>>(axh, axl, wb, b2, bufy, 256, 5, 0, 0);
    stats_kernel<<<BATCH, 256>>>(bufy);
    gather_fuse_kernel<<<ggath, 256>>>(bufy, axh, axl, g2, be2, 2);

    // gates GEMM: taps=1 at offset 2 (time t), mode 1
    prep_gw_kernel<<<256, 256>>>(kf, bf, kb, bb);
    mma_kernel<<<gmma, 256, SMEM_MMA>>>(axh, axl, wb, gbias, pre, 256, 1, 2, 1);

    lstm_kernel<<<dim3(32, 2), 256>>>(pre, rf, rb, (float*)d_out);
}

// round 9
// speedup vs baseline: 3.1942x; 1.1508x over previous
#include <cuda_runtime.h>
#include <cuda_fp16.h>
#include <math.h>
#include <stdint.h>

#define BATCH 256
#define TLEN  192
#define CENC  256
#define NGATE 128
#define NECK  32
#define TPAD  200
#define CPAD_MAX 320

// ---------------- scratch ----------------
__device__ float g_bufy[(size_t)BATCH * CENC * TLEN];            // conv output (B,C,T)
__device__ float g_pre [(size_t)2 * BATCH * TLEN * NGATE];       // lstm pre-gates
__device__ __half g_ax_hi[(size_t)BATCH * TPAD * CPAD_MAX];
__device__ __half g_ax_lo[(size_t)BATCH * TPAD * CPAD_MAX];
__device__ __half g_wb[(size_t)5 * CPAD_MAX * 256];              // (tap, c, co) fp16
__device__ float g_gbias[256];
__device__ float g_scale[3][1792];
__device__ int   g_len  [3][1792];
__device__ int   g_src  [3][BATCH][TLEN];
__device__ float g_lam  [3][BATCH][TLEN];
__device__ float g_mean [BATCH];
__device__ float g_istd [BATCH];

// ---------------- cp.async helpers ----------------
#define CP16(dst, src) \
    asm volatile("cp.async.cg.shared.global [%0], [%1], 16;" :: "r"(dst), "l"(src))
#define CPCOMMIT() asm volatile("cp.async.commit_group;")
#define CPWAIT1()  asm volatile("cp.async.wait_group 1;")
#define CPWAIT0()  asm volatile("cp.async.wait_group 0;")

__device__ __forceinline__ uint32_t smem_u32(const void* p) {
    uint32_t a;
    asm("{ .reg .u64 t; cvta.to.shared.u64 t, %1; cvt.u32.u64 %0, t; }" : "=r"(a) : "l"(p));
    return a;
}

// ---------------- threefry2x32 (bit-exact JAX PRNG) ----------------
__device__ __forceinline__ unsigned tf_rotl(unsigned v, int r) {
    return (v << r) | (v >> (32 - r));
}
__device__ __forceinline__ void threefry2x32(unsigned k0, unsigned k1,
                                             unsigned x0, unsigned x1,
                                             unsigned& o0, unsigned& o1) {
    unsigned ks2 = k0 ^ k1 ^ 0x1BD11BDAu;
    x0 += k0; x1 += k1;
#define TF_RND(r) { x0 += x1; x1 = tf_rotl(x1, r); x1 ^= x0; }
    TF_RND(13) TF_RND(15) TF_RND(26) TF_RND(6)
    x0 += k1;  x1 += ks2 + 1u;
    TF_RND(17) TF_RND(29) TF_RND(16) TF_RND(24)
    x0 += ks2; x1 += k0 + 2u;
    TF_RND(13) TF_RND(15) TF_RND(26) TF_RND(6)
    x0 += k0;  x1 += k1 + 3u;
    TF_RND(17) TF_RND(29) TF_RND(16) TF_RND(24)
    x0 += k1;  x1 += ks2 + 4u;
    TF_RND(13) TF_RND(15) TF_RND(26) TF_RND(6)
#undef TF_RND
    o0 = x0 + ks2;
    o1 = x1 + k0 + 5u;
}
__device__ __forceinline__ unsigned tf_bits32(unsigned ka, unsigned kb, unsigned i) {
    unsigned o0, o1;
    threefry2x32(ka, kb, 0u, i, o0, o1);
    return o0 ^ o1;
}

__global__ void rng_bits_kernel() {
    int id = blockIdx.x * blockDim.x + threadIdx.x;
    if (id >= 3 * 1792) return;
    int l = id / 1792, m = id % 1792;
    unsigned ka, kb;
    threefry2x32(0u, 42u, 0u, (unsigned)l, ka, kb);
    unsigned k1a, k1b, k2a, k2b;
    threefry2x32(ka, kb, 0u, 0u, k1a, k1b);
    threefry2x32(ka, kb, 0u, 1u, k2a, k2b);
    unsigned ub = tf_bits32(k1a, k1b, (unsigned)m);
    float u = __uint_as_float((ub >> 9) | 0x3f800000u) - 1.0f;
    g_scale[l][m] = fmaxf(0.5f, u + 0.5f);
    unsigned ha, hb_, la, lb_;
    threefry2x32(k2a, k2b, 0u, 0u, ha, hb_);
    threefry2x32(k2a, k2b, 0u, 1u, la, lb_);
    unsigned hbits = tf_bits32(ha, hb_, (unsigned)m);
    unsigned lbits = tf_bits32(la, lb_, (unsigned)m);
    unsigned off = ((hbits % 13u) * 9u + (lbits % 13u)) % 13u;
    g_len[l][m] = 19 + (int)off;
}

__global__ void rng_scan_kernel() {
    int id = blockIdx.x * blockDim.x + threadIdx.x;
    if (id >= 3 * BATCH) return;
    int l = id / BATCH, b = id % BATCH;
    int cnt = 0, off = 0;
    for (int s = 0; s < 7; s++) {
        int m = b * 7 + s;
        float scale = g_scale[l][m];
        int   L     = g_len[l][m];
        float Lm1   = (float)(L - 1);
        float offf  = (float)off;
        for (int j = 0; j < 64; j++) {
            float is = (float)j / scale;
            float fl = floorf(is);
            if (fl < Lm1 && (fl + offf) < 191.0f) {
                if (cnt < TLEN) {
                    g_src[l][b][cnt] = (int)(fl + offf);
                    g_lam[l][b][cnt] = is - fl;
                }
                cnt++;
            }
        }
        off += L;
    }
    for (int t = cnt; t < TLEN; t++) g_src[l][b][t] = -1;
}

// ---------------- prep_x (layer 0 only): fp32 (B,Csrc,192) -> fp16 hi/lo (B,200,Cpad) ----------------
__global__ __launch_bounds__(256)
void prep_x_kernel(const float* __restrict__ src, int Csrc, int Cpad,
                   __half* __restrict__ dhi, __half* __restrict__ dlo) {
    __shared__ float s[32][65];
    int c0 = blockIdx.x * 32;
    int t0 = blockIdx.y * 64;
    int b  = blockIdx.z;
    int tid = threadIdx.x;
    for (int i = tid; i < 32 * 64; i += 256) {
        int ci = i >> 6, tt = i & 63;
        int tsrc = t0 + tt - 2;
        float v = 0.f;
        int c = c0 + ci;
        if (c < Csrc && tsrc >= 0 && tsrc < TLEN)
            v = src[((size_t)b * Csrc + c) * TLEN + tsrc];
        s[ci][tt] = v;
    }
    __syncthreads();
    for (int i = tid; i < 64 * 32; i += 256) {
        int tdl = i >> 5, cl = i & 31;
        int td = t0 + tdl;
        if (td < TPAD) {
            float f = s[cl][tdl];
            __half hi = __float2half_rn(f);
            float lo = f - __half2float(hi);
            size_t o = ((size_t)b * TPAD + td) * Cpad + c0 + cl;
            dhi[o] = hi;
            dlo[o] = __float2half_rn(lo);
        }
    }
}

// ---------------- prep_w: fp32 (taps,Csrc,256) -> fp16 (taps,Cpad,256) ----------------
__global__ __launch_bounds__(256)
void prep_w_kernel(const float* __restrict__ w, int taps, int Csrc, int Cpad) {
    int n = gridDim.x * blockDim.x;
    int total = taps * Cpad * 256;
    for (int i = blockIdx.x * blockDim.x + threadIdx.x; i < total; i += n) {
        int tap = i / (Cpad * 256);
        int rem = i % (Cpad * 256);
        int c = rem / 256, co = rem % 256;
        float v = (c < Csrc) ? w[((size_t)tap * Csrc + c) * 256 + co] : 0.f;
        g_wb[i] = __float2half_rn(v);
    }
}

// ---------------- prep_gw: gates weight (1,256,256) + bias ----------------
__global__ __launch_bounds__(256)
void prep_gw_kernel(const float* __restrict__ kf, const float* __restrict__ bf,
                    const float* __restrict__ kb, const float* __restrict__ bb) {
    int i = blockIdx.x * blockDim.x + threadIdx.x;
    if (i < 256 * 256) {
        int c = i / 256, nn = i % 256;
        float v = (nn < 128) ? kf[(size_t)c * 128 + nn] : kb[(size_t)c * 128 + (nn - 128)];
        g_wb[i] = __float2half_rn(v);
        if (i < 256) g_gbias[i] = (i < 128) ? bf[i] : bb[i - 128];
    }
}

// ---------------- legacy-HMMA GEMM: W staged once per k-chunk, both splits fused ----------------
// Buffer layout per stage: W[TAPS][32][136] | Ahi[68][40] | Alo[68][40]
#define A_SZ 5440

template <int TAPS>
__global__ __launch_bounds__(256)
void mma_kernel(const __half* __restrict__ Ahi, const __half* __restrict__ Alo,
                const __half* __restrict__ Wgt,
                const float* __restrict__ bias, float* __restrict__ out,
                int Cpad, int tap_offset, int mode) {
    constexpr int W_SZ  = TAPS * 32 * 272;
    constexpr int BUFSZ = W_SZ + 2 * A_SZ;

    extern __shared__ char dsm[];
    const uint32_t sb = smem_u32(dsm);

    const int bn = blockIdx.x;      // n tile (128 wide)
    const int bm = blockIdx.y;      // m tile (64 wide)
    const int bb = blockIdx.z;      // batch
    const int tid  = threadIdx.x;
    const int wid  = tid >> 5;
    const int lane = tid & 31;
    const int warp_m = wid >> 3;    // 0..1  (wid/8? no) -- keep 2x4 split below
    const int wm = wid >> 2;        // 0..1
    const int wn = wid & 3;         // 0..3
    const int t0 = bm * 64;
    const int n0 = bn * 128;
    (void)warp_m;

    float acc[2][4][4];
#pragma unroll
    for (int i = 0; i < 2; i++)
#pragma unroll
        for (int j = 0; j < 4; j++)
#pragma unroll
            for (int k = 0; k < 4; k++) acc[i][j][k] = 0.f;

    const int kchunks = Cpad >> 5;
    const int rs = Cpad >> 3;               // uint4 per activation row

    auto stage = [&](int it) {
        uint32_t buf = sb + (uint32_t)(it & 1) * BUFSZ;
        int k0 = it * 32;
        for (int i = tid; i < TAPS * 512; i += 256) {
            int tp = i >> 9, r = (i >> 4) & 31, q = i & 15;
            const uint4* srcW = (const uint4*)(Wgt + ((size_t)tp * Cpad + k0 + r) * 256 + n0);
            CP16(buf + (uint32_t)((tp * 32 + r) * 272 + q * 16), srcW + q);
        }
        const uint4* srcH = (const uint4*)(Ahi + ((size_t)bb * TPAD + t0) * Cpad + k0);
        const uint4* srcL = (const uint4*)(Alo + ((size_t)bb * TPAD + t0) * Cpad + k0);
        for (int i = tid; i < 272; i += 256) {
            int r = i >> 2, q = i & 3;
            CP16(buf + W_SZ + (uint32_t)(r * 80 + q * 16), srcH + (size_t)r * rs + q);
        }
        for (int i = tid; i < 272; i += 256) {
            int r = i >> 2, q = i & 3;
            CP16(buf + W_SZ + A_SZ + (uint32_t)(r * 80 + q * 16), srcL + (size_t)r * rs + q);
        }
    };

    stage(0);
    CPCOMMIT();

    for (int it = 0; it < kchunks; it++) {
        if (it + 1 < kchunks) {
            stage(it + 1);
            CPCOMMIT();
            CPWAIT1();
        } else {
            CPWAIT0();
        }
        __syncthreads();

        uint32_t buf  = sb + (uint32_t)(it & 1) * BUFSZ;
        uint32_t sahi = buf + W_SZ;
        uint32_t salo = sahi + A_SZ;

#pragma unroll
        for (int tp = 0; tp < TAPS; tp++) {
            int cshift = tap_offset + tp;
#pragma unroll
            for (int kstep = 0; kstep < 2; kstep++) {
                unsigned ah[2][4], al[2][4];
#pragma unroll
                for (int mt = 0; mt < 2; mt++) {
                    int row = wm * 32 + mt * 16 + cshift + (lane & 15);
                    int col = kstep * 16 + ((lane >> 4) * 8);
                    uint32_t adr_h = sahi + (uint32_t)(row * 80 + col * 2);
                    uint32_t adr_l = salo + (uint32_t)(row * 80 + col * 2);
                    asm volatile("ldmatrix.sync.aligned.m8n8.x4.shared.b16 {%0,%1,%2,%3}, [%4];"
                                 : "=r"(ah[mt][0]), "=r"(ah[mt][1]), "=r"(ah[mt][2]), "=r"(ah[mt][3])
                                 : "r"(adr_h));
                    asm volatile("ldmatrix.sync.aligned.m8n8.x4.shared.b16 {%0,%1,%2,%3}, [%4];"
                                 : "=r"(al[mt][0]), "=r"(al[mt][1]), "=r"(al[mt][2]), "=r"(al[mt][3])
                                 : "r"(adr_l));
                }
                unsigned bfr[4][2];
#pragma unroll
                for (int np = 0; np < 2; np++) {
                    int row = kstep * 16 + (lane & 15);
                    int col = wn * 32 + np * 16 + ((lane >= 16) ? 8 : 0);
                    uint32_t addr = buf + (uint32_t)((tp * 32 + row) * 272 + col * 2);
                    unsigned r0, r1, r2, r3;
                    asm volatile("ldmatrix.sync.aligned.m8n8.x4.trans.shared.b16 {%0,%1,%2,%3}, [%4];"
                                 : "=r"(r0), "=r"(r1), "=r"(r2), "=r"(r3)
                                 : "r"(addr));
                    bfr[np * 2 + 0][0] = r0; bfr[np * 2 + 0][1] = r1;
                    bfr[np * 2 + 1][0] = r2; bfr[np * 2 + 1][1] = r3;
                }
#pragma unroll
                for (int mt = 0; mt < 2; mt++)
#pragma unroll
                    for (int nt = 0; nt < 4; nt++) {
                        asm volatile(
                            "mma.sync.aligned.m16n8k16.row.col.f32.f16.f16.f32 "
                            "{%0,%1,%2,%3},{%4,%5,%6,%7},{%8,%9},{%0,%1,%2,%3};"
                            : "+f"(acc[mt][nt][0]), "+f"(acc[mt][nt][1]),
                              "+f"(acc[mt][nt][2]), "+f"(acc[mt][nt][3])
                            : "r"(ah[mt][0]), "r"(ah[mt][1]), "r"(ah[mt][2]), "r"(ah[mt][3]),
                              "r"(bfr[nt][0]), "r"(bfr[nt][1]));
                        asm volatile(
                            "mma.sync.aligned.m16n8k16.row.col.f32.f16.f16.f32 "
                            "{%0,%1,%2,%3},{%4,%5,%6,%7},{%8,%9},{%0,%1,%2,%3};"
                            : "+f"(acc[mt][nt][0]), "+f"(acc[mt][nt][1]),
                              "+f"(acc[mt][nt][2]), "+f"(acc[mt][nt][3])
                            : "r"(al[mt][0]), "r"(al[mt][1]), "r"(al[mt][2]), "r"(al[mt][3]),
                              "r"(bfr[nt][0]), "r"(bfr[nt][1]));
                    }
            }
        }
        __syncthreads();
    }

    // epilogue
    int gid = lane >> 2, tig = lane & 3;
#pragma unroll
    for (int mt = 0; mt < 2; mt++) {
#pragma unroll
        for (int nt = 0; nt < 4; nt++) {
            int t  = t0 + wm * 32 + mt * 16 + gid;
            int co = n0 + wn * 32 + nt * 8 + tig * 2;
            float bv0 = bias[co], bv1 = bias[co + 1];
            if (mode == 0) {
                float* yp0 = out + ((size_t)bb * 256 + co) * TLEN;
                float* yp1 = yp0 + TLEN;
                yp0[t]     = acc[mt][nt][0] + bv0;
                yp1[t]     = acc[mt][nt][1] + bv1;
                yp0[t + 8] = acc[mt][nt][2] + bv0;
                yp1[t + 8] = acc[mt][nt][3] + bv1;
            } else {
                int dir0 = co >> 7, g0 = co & 127;
                int dir1 = (co + 1) >> 7, g1 = (co + 1) & 127;
                size_t r0 = ((size_t)(dir0 * BATCH + bb) * TLEN + t) * NGATE + g0;
                size_t r1 = ((size_t)(dir1 * BATCH + bb) * TLEN + t) * NGATE + g1;
                out[r0] = acc[mt][nt][0] + bv0;
                out[r1] = acc[mt][nt][1] + bv1;
                size_t r2 = ((size_t)(dir0 * BATCH + bb) * TLEN + t + 8) * NGATE + g0;
                size_t r3 = ((size_t)(dir1 * BATCH + bb) * TLEN + t + 8) * NGATE + g1;
                out[r2] = acc[mt][nt][2] + bv0;
                out[r3] = acc[mt][nt][3] + bv1;
            }
        }
    }
}

// ---------------- per-sample mean/istd over (C,T), fp32 ----------------
__global__ __launch_bounds__(256)
void stats_kernel(const float* __restrict__ y) {
    int b = blockIdx.x;
    const float4* p = (const float4*)(y + (size_t)b * CENC * TLEN);
    float s0 = 0.f, s1 = 0.f, q0 = 0.f, q1 = 0.f;
    for (int i = threadIdx.x; i < CENC * TLEN / 4; i += 256) {
        float4 v = p[i];
        s0 += v.x + v.y;
        s1 += v.z + v.w;
        q0 = fmaf(v.x, v.x, fmaf(v.y, v.y, q0));
        q1 = fmaf(v.z, v.z, fmaf(v.w, v.w, q1));
    }
    float s = s0 + s1, q = q0 + q1;
    __shared__ float sh[256], sh2[256];
    sh[threadIdx.x] = s; sh2[threadIdx.x] = q;
    __syncthreads();
    for (int k = 128; k > 0; k >>= 1) {
        if (threadIdx.x < k) { sh[threadIdx.x] += sh[threadIdx.x + k]; sh2[threadIdx.x] += sh2[threadIdx.x + k]; }
        __syncthreads();
    }
    if (threadIdx.x == 0) {
        float mm = sh[0] / (float)(CENC * TLEN);
        float var = sh2[0] / (float)(CENC * TLEN) - mm * mm;
        g_mean[b] = mm;
        g_istd[b] = rsqrtf(var + 1e-5f);
    }
}

// ---------------- fused GN + ReLU + interp gather + fp16 hi/lo transpose ----------------
__global__ __launch_bounds__(256)
void gather_fuse_kernel(const float* __restrict__ y,
                        __half* __restrict__ dhi, __half* __restrict__ dlo,
                        const float* __restrict__ gamma, const float* __restrict__ beta,
                        int layer) {
    __shared__ float s[TLEN][33];
    int b = blockIdx.x, cz = blockIdx.y;
    int c0 = cz * 32;
    float mean = g_mean[b], istd = g_istd[b];
    int tid = threadIdx.x;

    for (int i = tid; i < 32 * TLEN; i += 256) {
        int ci = i / TLEN;
        int t = i % TLEN;
        int src = g_src[layer][b][t];
        float v = 0.f;
        if (src >= 0) {
            float lam = g_lam[layer][b][t];
            const float* yr = y + ((size_t)b * CENC + c0 + ci) * TLEN;
            float r0 = fmaxf((yr[src]     - mean) * istd * gamma[src]     + beta[src],     0.f);
            float r1 = fmaxf((yr[src + 1] - mean) * istd * gamma[src + 1] + beta[src + 1], 0.f);
            v = (1.f - lam) * r0 + lam * r1;
        }
        s[t][ci] = v;
    }
    __syncthreads();

    for (int i = tid; i < TLEN * 32; i += 256) {
        int t = i >> 5, ci = i & 31;
        float f = s[t][ci];
        __half hi = __float2half_rn(f);
        float lo = f - __half2float(hi);
        size_t o = ((size_t)b * TPAD + t + 2) * CENC + c0 + ci;
        dhi[o] = hi;
        dlo[o] = __float2half_rn(lo);
    }
    if (tid < 256) {
        const int padrows[8] = {0, 1, 194, 195, 196, 197, 198, 199};
        int pr = padrows[tid >> 5], ci = tid & 31;
        size_t o = ((size_t)b * TPAD + pr) * CENC + c0 + ci;
        dhi[o] = __float2half_rn(0.f);
        dlo[o] = __float2half_rn(0.f);
    }
}

// ---------------- LSTM recurrence ----------------
__device__ __forceinline__ float sigm(float x) { return 1.f / (1.f + expf(-x)); }

__global__ __launch_bounds__(256)
void lstm_kernel(const float* __restrict__ pre,
                 const float* __restrict__ rf, const float* __restrict__ rb,
                 float* __restrict__ out) {
    __shared__ __align__(16) float Rs[32][128];
    int dir = blockIdx.y;
    const float* R = dir ? rb : rf;
    for (int i = threadIdx.x; i < 32 * 128; i += 256) Rs[i >> 7][i & 127] = R[i];
    __syncthreads();

    int warp = threadIdx.x >> 5, lane = threadIdx.x & 31;
    int b = blockIdx.x * 8 + warp;
    float h = 0.f, c = 0.f;
    const float* preb = pre + (((size_t)dir * BATCH + b) * TLEN) * NGATE;

    for (int s = 0; s < TLEN; s++) {
        int t = dir ? (TLEN - 1 - s) : s;
        const float* p = preb + (size_t)t * NGATE;
        float zi = p[lane], zf = p[32 + lane], zg = p[64 + lane], zo = p[96 + lane];
#pragma unroll
        for (int j = 0; j < 32; j++) {
            float hj = __shfl_sync(0xffffffffu, h, j);
            zi += hj * Rs[j][lane];
            zf += hj * Rs[j][32 + lane];
            zg += hj * Rs[j][64 + lane];
            zo += hj * Rs[j][96 + lane];
        }
        c = sigm(zf) * c + sigm(zi) * tanhf(zg);
        h = sigm(zo) * tanhf(c);
        out[((size_t)b * TLEN + t) * 64 + dir * 32 + lane] = h;
    }
}

// ---------------- launch ----------------
extern "C" void kernel_launch(void* const* d_in, const int* in_sizes, int n_in,
                              void* d_out, int out_size) {
    const float* x   = (const float*)d_in[0];
    const float* w0  = (const float*)d_in[1];
    const float* b0  = (const float*)d_in[2];
    const float* w1  = (const float*)d_in[3];
    const float* b1  = (const float*)d_in[4];
    const float* w2  = (const float*)d_in[5];
    const float* b2  = (const float*)d_in[6];
    const float* g0  = (const float*)d_in[7];
    const float* be0 = (const float*)d_in[8];
    const float* g1  = (const float*)d_in[9];
    const float* be1 = (const float*)d_in[10];
    const float* g2  = (const float*)d_in[11];
    const float* be2 = (const float*)d_in[12];
    const float* kf  = (const float*)d_in[13];
    const float* rf  = (const float*)d_in[14];
    const float* bf  = (const float*)d_in[15];
    const float* kb  = (const float*)d_in[16];
    const float* rb  = (const float*)d_in[17];
    const float* bb  = (const float*)d_in[18];

    float *bufy, *pre, *gbias;
    __half *axh, *axl, *wb;
    cudaGetSymbolAddress((void**)&bufy, g_bufy);
    cudaGetSymbolAddress((void**)&pre,  g_pre);
    cudaGetSymbolAddress((void**)&gbias, g_gbias);
    cudaGetSymbolAddress((void**)&axh, g_ax_hi);
    cudaGetSymbolAddress((void**)&axl, g_ax_lo);
    cudaGetSymbolAddress((void**)&wb,  g_wb);

    const int SMEM5 = 2 * (5 * 32 * 272 + 2 * A_SZ);   // 108800
    const int SMEM1 = 2 * (1 * 32 * 272 + 2 * A_SZ);   // 39168
    cudaFuncSetAttribute(mma_kernel<5>, cudaFuncAttributeMaxDynamicSharedMemorySize, SMEM5);
    cudaFuncSetAttribute(mma_kernel<1>, cudaFuncAttributeMaxDynamicSharedMemorySize, SMEM1);

    rng_bits_kernel<<<21, 256>>>();
    rng_scan_kernel<<<3, 256>>>();

    dim3 gmma(2, 3, BATCH);
    dim3 ggath(BATCH, 8);

    // layer 0 (Csrc=257, Cpad=320)
    prep_w_kernel<<<320, 256>>>(w0, 5, 257, 320);
    prep_x_kernel<<<dim3(10, 4, BATCH), 256>>>(x, 257, 320, axh, axl);
    mma_kernel<5><<<gmma, 256, SMEM5>>>(axh, axl, wb, b0, bufy, 320, 0, 0);
    stats_kernel<<<BATCH, 256>>>(bufy);
    gather_fuse_kernel<<<ggath, 256>>>(bufy, axh, axl, g0, be0, 0);
    // layer 1 (Cpad=256)
    prep_w_kernel<<<256, 256>>>(w1, 5, 256, 256);
    mma_kernel<5><<<gmma, 256, SMEM5>>>(axh, axl, wb, b1, bufy, 256, 0, 0);
    stats_kernel<<<BATCH, 256>>>(bufy);
    gather_fuse_kernel<<<ggath, 256>>>(bufy, axh, axl, g1, be1, 1);
    // layer 2
    prep_w_kernel<<<256, 256>>>(w2, 5, 256, 256);
    mma_kernel<5><<<gmma, 256, SMEM5>>>(axh, axl, wb, b2, bufy, 256, 0, 0);
    stats_kernel<<<BATCH, 256>>>(bufy);
    gather_fuse_kernel<<<ggath, 256>>>(bufy, axh, axl, g2, be2, 2);

    // gates GEMM: taps=1 at offset 2 (time t), mode 1
    prep_gw_kernel<<<256, 256>>>(kf, bf, kb, bb);
    mma_kernel<1><<<gmma, 256, SMEM1>>>(axh, axl, wb, gbias, pre, 256, 2, 1);

    lstm_kernel<<<dim3(32, 2), 256>>>(pre, rf, rb, (float*)d_out);
}